// round 13
// baseline (speedup 1.0000x reference)
#include <cuda_runtime.h>
#include <cuda_fp16.h>
#include <cstdint>

// Problem constants
#define BB   2
#define QQ   1024
#define MEMN 1024
#define UU   1024
#define HH   16
#define DHH  64
#define KL   2048   // MEM + Q
#define KSPLIT 3

// ---------------------------------------------------------------------------
// Scratch (allocation-free: __device__ globals, 16B-aligned for cp.async)
// ---------------------------------------------------------------------------
__device__ __align__(16) __half g_fullh[(size_t)BB * KL * UU];     // fp16 concat
__device__ __align__(16) __half g_relrh[(size_t)BB * KL * UU];     // fp16 relatives
__device__ __align__(16) __half g_qch [(size_t)BB * QQ * UU];      // fp16 q + bias_c
__device__ __align__(16) __half g_qrh [(size_t)BB * QQ * UU];      // fp16 q + bias_r
__device__ __align__(16) __half g_kh  [(size_t)BB * KL * UU];      // fp16 K
__device__ __align__(16) __half g_vh  [(size_t)BB * KL * UU];      // fp16 V  [b,t,u]
__device__ __align__(16) __half g_wrh [(size_t)BB * KL * UU];      // fp16 w_r
__device__ __align__(16) __half g_srh [(size_t)BB * HH * QQ * KL]; // fp16 Sr SHIFTED
__device__ __align__(16) __half g_ctxh[(size_t)BB * QQ * UU];      // fp16 attention out
__device__ __align__(16) __half g_wqTh [(size_t)UU * UU];
__device__ __align__(16) __half g_wkvTh[(size_t)2 * UU * UU];
__device__ __align__(16) __half g_wrTh [(size_t)UU * UU];
__device__ __align__(16) __half g_woTh [(size_t)UU * UU];
__device__ float g_opart[(size_t)BB * HH * QQ * KSPLIT * DHH];
__device__ float g_ml   [(size_t)BB * HH * QQ * KSPLIT * 2];

// ---------------------------------------------------------------------------
// Helpers
// ---------------------------------------------------------------------------
__device__ __forceinline__ uint32_t smem_to_u32(const void* p) {
    uint32_t a;
    asm("{ .reg .u64 t; cvta.to.shared.u64 t, %1; cvt.u32.u64 %0, t; }" : "=r"(a) : "l"(p));
    return a;
}
__device__ __forceinline__ void cp_async16(uint32_t saddr, const void* gaddr) {
    asm volatile("cp.async.cg.shared.global [%0], [%1], 16;" :: "r"(saddr), "l"(gaddr));
}
#define CP_COMMIT() asm volatile("cp.async.commit_group;" ::: "memory")
#define CP_WAIT0()  asm volatile("cp.async.wait_group 0;" ::: "memory")
#define CP_WAIT1()  asm volatile("cp.async.wait_group 1;" ::: "memory")
#define CP_WAIT2()  asm volatile("cp.async.wait_group 2;" ::: "memory")

__device__ __forceinline__ void mma_f16(float acc[4], const uint32_t a[4], const uint32_t b[2]) {
    asm volatile("mma.sync.aligned.m16n8k16.row.col.f32.f16.f16.f32 "
        "{%0,%1,%2,%3}, {%4,%5,%6,%7}, {%8,%9}, {%0,%1,%2,%3};"
        : "+f"(acc[0]), "+f"(acc[1]), "+f"(acc[2]), "+f"(acc[3])
        : "r"(a[0]), "r"(a[1]), "r"(a[2]), "r"(a[3]), "r"(b[0]), "r"(b[1]));
}
__device__ __forceinline__ void ldsm_x4(uint32_t* r, uint32_t addr) {
    asm volatile("ldmatrix.sync.aligned.m8n8.x4.shared.b16 {%0,%1,%2,%3}, [%4];"
        : "=r"(r[0]), "=r"(r[1]), "=r"(r[2]), "=r"(r[3]) : "r"(addr));
}
__device__ __forceinline__ void ldsm_x4t(uint32_t* r, uint32_t addr) {
    asm volatile("ldmatrix.sync.aligned.m8n8.x4.trans.shared.b16 {%0,%1,%2,%3}, [%4];"
        : "=r"(r[0]), "=r"(r[1]), "=r"(r[2]), "=r"(r[3]) : "r"(addr));
}

// ---------------------------------------------------------------------------
// prep: concat(memories, inputs) -> g_fullh ; relatives -> g_relrh (fp16)
// ---------------------------------------------------------------------------
__global__ void prep_kernel(const float* __restrict__ mem,
                            const float* __restrict__ inp,
                            const float* __restrict__ rel) {
    const size_t total4 = (size_t)BB * KL * UU / 4;
    size_t i = (size_t)blockIdx.x * blockDim.x + threadIdx.x;
    if (i < total4) {
        size_t elem = i * 4;
        int b = (int)(elem / ((size_t)KL * UU));
        size_t rem = elem % ((size_t)KL * UU);
        int t = (int)(rem / UU);
        int u = (int)(rem % UU);
        float4 v;
        if (t < MEMN) v = *(const float4*)(mem + ((size_t)b * MEMN + t) * UU + u);
        else          v = *(const float4*)(inp + ((size_t)b * QQ + (t - MEMN)) * UU + u);
        __half2* o = (__half2*)(g_fullh + elem);
        o[0] = __floats2half2_rn(v.x, v.y);
        o[1] = __floats2half2_rn(v.z, v.w);
    } else if (i < 2 * total4) {
        size_t j = i - total4;
        float4 v = ((const float4*)rel)[j];
        __half2* o = (__half2*)(g_relrh + j * 4);
        o[0] = __floats2half2_rn(v.x, v.y);
        o[1] = __floats2half2_rn(v.z, v.w);
    }
}

// ---------------------------------------------------------------------------
// Fused weight transposes: W[K=1024, N] row-major -> W^T[N, 1024] fp16
// ---------------------------------------------------------------------------
__global__ void wtrans_kernel(const float* __restrict__ Wq, const float* __restrict__ Wkv,
                              const float* __restrict__ Wr, const float* __restrict__ Wo) {
    __shared__ float t[32][33];
    int bid = blockIdx.x;
    const float* in; __half* out; int cols;
    if (bid < 1024)      { in = Wq;  out = g_wqTh;  cols = 1024; }
    else if (bid < 3072) { in = Wkv; out = g_wkvTh; cols = 2048; bid -= 1024; }
    else if (bid < 4096) { in = Wr;  out = g_wrTh;  cols = 1024; bid -= 3072; }
    else                 { in = Wo;  out = g_woTh;  cols = 1024; bid -= 4096; }
    int tilesX = cols / 32;
    int c0 = (bid % tilesX) * 32;
    int r0 = (bid / tilesX) * 32;
    int tx = threadIdx.x, ty = threadIdx.y;
#pragma unroll
    for (int i = 0; i < 32; i += 8)
        t[ty + i][tx] = in[(size_t)(r0 + ty + i) * cols + c0 + tx];
    __syncthreads();
#pragma unroll
    for (int i = 0; i < 32; i += 8)
        out[(size_t)(c0 + ty + i) * 1024 + r0 + tx] = __float2half(t[tx][ty + i]);
}

// ===========================================================================
// Shared GEMM constants (BM=BN=128, WM=64, WN=32, KC=32)
// ===========================================================================
#define G_LDSS 40
#define G_KC   32

// ---------------------------------------------------------------------------
// Merged projection GEMM: one launch covers wkv (EPI4), wr (EPI3), wq (EPI2).
// Flat grid: [0,512) wkv | [512,768) wr | [768,896) wq. 4-stage pipeline.
// ---------------------------------------------------------------------------
__global__ void __launch_bounds__(256)
proj_kernel(const float* __restrict__ bc, const float* __restrict__ br) {
    constexpr int BM = 128, BN = 128, WM = 64, WN = 32;
    constexpr int MFRAG = WM / 16, NFRAG = WN / 8;

    int cta = blockIdx.x;
    int epi;
    const __half* A;
    const __half* Bw;
    __half *Ch = nullptr, *C2h = nullptr;
    int bm, bn;
    if (cta < 512) {               // wkv
        epi = 4;
        int bx = cta & 15, by = cta >> 4;
        A = g_fullh; Bw = g_wkvTh;
        Ch = g_vh; C2h = g_kh;
        bm = by * BM; bn = bx * BN;
    } else if (cta < 768) {        // wr
        epi = 3;
        int c = cta - 512;
        int bx = c & 7, by = c >> 3;
        A = g_relrh; Bw = g_wrTh;
        Ch = g_wrh;
        bm = by * BM; bn = bx * BN;
    } else {                       // wq
        epi = 2;
        int c = cta - 768;
        int bx = c & 7, by = (c >> 3) & 7, zz = c >> 6;
        A = g_fullh + (size_t)MEMN * UU + (size_t)zz * KL * UU;
        Bw = g_wqTh;
        Ch = g_qch + (size_t)zz * QQ * UU;
        C2h = g_qrh + (size_t)zz * QQ * UU;
        bm = by * BM; bn = bx * BN;
    }
    const int lda = UU, ldb = UU, ldc = UU;
    const int nIter = UU / G_KC;   // 32

    extern __shared__ __half smh[];
    __half* As = smh;
    __half* Bs = smh + 4 * BM * G_LDSS;
    const uint32_t sA_base = smem_to_u32(As);
    const uint32_t sB_base = smem_to_u32(Bs);

    const int tid = threadIdx.x;
    const int lane = tid & 31;
    const int warp = tid >> 5;
    const int wm = warp & 1;
    const int wn = warp >> 1;
    const __half* Ag = A + (size_t)bm * lda;
    const __half* Bg = Bw + (size_t)bn * ldb;

    auto load_stage = [&](int stage, int buf) {
#pragma unroll
        for (int i = 0; i < 2; i++) {
            int idx = tid + i * 256;
            int row = idx >> 2, ch = idx & 3;
            uint32_t s = sA_base + (uint32_t)(buf * BM * G_LDSS + row * G_LDSS + ch * 8) * 2u;
            cp_async16(s, Ag + (size_t)row * lda + stage * G_KC + ch * 8);
        }
#pragma unroll
        for (int i = 0; i < 2; i++) {
            int idx = tid + i * 256;
            int row = idx >> 2, ch = idx & 3;
            uint32_t s = sB_base + (uint32_t)(buf * BN * G_LDSS + row * G_LDSS + ch * 8) * 2u;
            cp_async16(s, Bg + (size_t)row * ldb + stage * G_KC + ch * 8);
        }
    };

    float acc[MFRAG][NFRAG][4];
#pragma unroll
    for (int i = 0; i < MFRAG; i++)
#pragma unroll
        for (int j = 0; j < NFRAG; j++)
#pragma unroll
            for (int v = 0; v < 4; v++) acc[i][j][v] = 0.0f;

    load_stage(0, 0); CP_COMMIT();
    load_stage(1, 1); CP_COMMIT();
    load_stage(2, 2); CP_COMMIT();

    const uint32_t aOff = (uint32_t)((wm * WM + (lane & 15)) * G_LDSS + (lane >> 4) * 8);
    const uint32_t bOff = (uint32_t)((wn * WN + (lane & 7) + (lane >> 4) * 8) * G_LDSS +
                                     ((lane >> 3) & 1) * 8);
    const int r4 = lane >> 2;
    const int c4 = lane & 3;

    for (int it = 0; it < nIter; ++it) {
        CP_WAIT2();
        __syncthreads();
        if (it + 3 < nIter) load_stage(it + 3, (it + 3) & 3);
        CP_COMMIT();

        const uint32_t aBuf = sA_base + (uint32_t)((it & 3) * BM * G_LDSS) * 2u;
        const uint32_t bBuf = sB_base + (uint32_t)((it & 3) * BN * G_LDSS) * 2u;

#pragma unroll
        for (int ks = 0; ks < 2; ks++) {
            uint32_t af[MFRAG][4];
            uint32_t bf[NFRAG][2];
#pragma unroll
            for (int fm = 0; fm < MFRAG; fm++)
                ldsm_x4(af[fm], aBuf + (aOff + fm * 16 * G_LDSS + ks * 16) * 2u);
#pragma unroll
            for (int fp = 0; fp < NFRAG / 2; fp++) {
                uint32_t r[4];
                ldsm_x4(r, bBuf + (bOff + fp * 16 * G_LDSS + ks * 16) * 2u);
                bf[2 * fp][0] = r[0]; bf[2 * fp][1] = r[1];
                bf[2 * fp + 1][0] = r[2]; bf[2 * fp + 1][1] = r[3];
            }
#pragma unroll
            for (int fm = 0; fm < MFRAG; fm++)
#pragma unroll
                for (int fn = 0; fn < NFRAG; fn++)
                    mma_f16(acc[fm][fn], af[fm], bf[fn]);
        }
    }

    const int m0 = bm + wm * WM;
    const int n0 = bn + wn * WN;
#pragma unroll
    for (int fm = 0; fm < MFRAG; fm++) {
#pragma unroll
        for (int fn = 0; fn < NFRAG; fn++) {
            int r = m0 + fm * 16 + r4;
            int cidx = n0 + fn * 8 + c4 * 2;
            float a0 = acc[fm][fn][0], a1 = acc[fm][fn][1];
            float a2 = acc[fm][fn][2], a3 = acc[fm][fn][3];
            if (epi == 4) {
                if (cidx < UU) {
                    *(__half2*)(C2h + (size_t)r * UU + cidx) = __floats2half2_rn(a0, a1);
                    *(__half2*)(C2h + (size_t)(r + 8) * UU + cidx) = __floats2half2_rn(a2, a3);
                } else {
                    *(__half2*)(Ch + (size_t)r * UU + cidx - UU) = __floats2half2_rn(a0, a1);
                    *(__half2*)(Ch + (size_t)(r + 8) * UU + cidx - UU) = __floats2half2_rn(a2, a3);
                }
            } else if (epi == 3) {
                *(__half2*)(Ch + (size_t)r * ldc + cidx) = __floats2half2_rn(a0, a1);
                *(__half2*)(Ch + (size_t)(r + 8) * ldc + cidx) = __floats2half2_rn(a2, a3);
            } else {  // epi == 2
                float b0 = bc[cidx], b1 = bc[cidx + 1];
                float r0 = br[cidx], r1 = br[cidx + 1];
                *(__half2*)(Ch + (size_t)r * ldc + cidx) = __floats2half2_rn(a0 + b0, a1 + b1);
                *(__half2*)(Ch + (size_t)(r + 8) * ldc + cidx) = __floats2half2_rn(a2 + b0, a3 + b1);
                *(__half2*)(C2h + (size_t)r * ldc + cidx) = __floats2half2_rn(a0 + r0, a1 + r1);
                *(__half2*)(C2h + (size_t)(r + 8) * ldc + cidx) = __floats2half2_rn(a2 + r0, a3 + r1);
            }
        }
    }
}

// ---------------------------------------------------------------------------
// Sr shifted GEMM, K=64 specialized: 2 flat K-chunks, SMEM-staged shifted
// store with 4-half-per-thread vectorized writes. Grid (KL/128, QQ/128, BB*HH).
// ---------------------------------------------------------------------------
__global__ void __launch_bounds__(256)
sr_kernel() {
    constexpr int BM = 128, BN = 128, WM = 64, WN = 32;
    constexpr int MFRAG = WM / 16, NFRAG = WN / 8;

    const int bm = blockIdx.y * BM;
    const int bn = blockIdx.x * BN;
    if (bn + bm + BM + BN - 2 - (QQ - 1) < 0) return;  // fully below shift diagonal

    const int z = blockIdx.z;          // b*HH + h
    const int z1 = z / HH, z2 = z % HH;
    const __half* A = g_qrh + (size_t)z1 * QQ * UU + (size_t)z2 * 64;
    const __half* B = g_wrh + (size_t)z1 * KL * UU + (size_t)z2 * 64;
    __half* C = g_srh + (size_t)z * QQ * KL;

    extern __shared__ __half smh[];
    __half* As = smh;                       // [2][128][40]
    __half* Bs = smh + 2 * BM * G_LDSS;     // [2][128][40]
    const uint32_t sA_base = smem_to_u32(As);
    const uint32_t sB_base = smem_to_u32(Bs);

    const int tid = threadIdx.x;
    const int lane = tid & 31;
    const int warp = tid >> 5;
    const int wm = warp & 1;
    const int wn = warp >> 1;
    const __half* Ag = A + (size_t)bm * UU;
    const __half* Bg = B + (size_t)bn * UU;

    // load both K chunks
#pragma unroll
    for (int st = 0; st < 2; st++) {
#pragma unroll
        for (int i = 0; i < 2; i++) {
            int idx = tid + i * 256;
            int row = idx >> 2, ch = idx & 3;
            cp_async16(sA_base + (uint32_t)(st * BM * G_LDSS + row * G_LDSS + ch * 8) * 2u,
                       Ag + (size_t)row * UU + st * G_KC + ch * 8);
        }
#pragma unroll
        for (int i = 0; i < 2; i++) {
            int idx = tid + i * 256;
            int row = idx >> 2, ch = idx & 3;
            cp_async16(sB_base + (uint32_t)(st * BN * G_LDSS + row * G_LDSS + ch * 8) * 2u,
                       Bg + (size_t)row * UU + st * G_KC + ch * 8);
        }
        CP_COMMIT();
    }
    CP_WAIT0();
    __syncthreads();

    const uint32_t aOff = (uint32_t)((wm * WM + (lane & 15)) * G_LDSS + (lane >> 4) * 8);
    const uint32_t bOff = (uint32_t)((wn * WN + (lane & 7) + (lane >> 4) * 8) * G_LDSS +
                                     ((lane >> 3) & 1) * 8);
    const int r4 = lane >> 2;
    const int c4 = lane & 3;

    float acc[MFRAG][NFRAG][4];
#pragma unroll
    for (int i = 0; i < MFRAG; i++)
#pragma unroll
        for (int j = 0; j < NFRAG; j++)
#pragma unroll
            for (int v = 0; v < 4; v++) acc[i][j][v] = 0.0f;

#pragma unroll
    for (int st = 0; st < 2; st++) {
        const uint32_t aBuf = sA_base + (uint32_t)(st * BM * G_LDSS) * 2u;
        const uint32_t bBuf = sB_base + (uint32_t)(st * BN * G_LDSS) * 2u;
#pragma unroll
        for (int ks = 0; ks < 2; ks++) {
            uint32_t af[MFRAG][4];
            uint32_t bf[NFRAG][2];
#pragma unroll
            for (int fm = 0; fm < MFRAG; fm++)
                ldsm_x4(af[fm], aBuf + (aOff + fm * 16 * G_LDSS + ks * 16) * 2u);
#pragma unroll
            for (int fp = 0; fp < NFRAG / 2; fp++) {
                uint32_t r[4];
                ldsm_x4(r, bBuf + (bOff + fp * 16 * G_LDSS + ks * 16) * 2u);
                bf[2 * fp][0] = r[0]; bf[2 * fp][1] = r[1];
                bf[2 * fp + 1][0] = r[2]; bf[2 * fp + 1][1] = r[3];
            }
#pragma unroll
            for (int fm = 0; fm < MFRAG; fm++)
#pragma unroll
                for (int fn = 0; fn < NFRAG; fn++)
                    mma_f16(acc[fm][fn], af[fm], bf[fn]);
        }
    }

    // ---- stage C tile in SMEM [128][136] (reuse A/B buffers) ----
    __syncthreads();
    __half* Cs = smh;
    const int m0l = wm * WM;
    const int n0l = wn * WN;
#pragma unroll
    for (int fm = 0; fm < MFRAG; fm++) {
#pragma unroll
        for (int fn = 0; fn < NFRAG; fn++) {
            int lr = m0l + fm * 16 + r4;
            int lc = n0l + fn * 8 + 2 * c4;
            *(__half2*)(Cs + lr * 136 + lc) =
                __floats2half2_rn(acc[fm][fn][0], acc[fm][fn][1]);
            *(__half2*)(Cs + (lr + 8) * 136 + lc) =
                __floats2half2_rn(acc[fm][fn][2], acc[fm][fn][3]);
        }
    }
    __syncthreads();

    // ---- coalesced shifted store: 4 halfs/thread, warp-uniform row ----
    const int col4 = lane * 4;            // 0..124
    const int off = bn - (QQ - 1) + bm;   // k of (row 0, col 0)
    int r = warp;                          // rows warp, warp+8, ..., warp+120
#pragma unroll
    for (int itr = 0; itr < 16; itr++, r += 8) {
        int k = off + r + col4;
        uint2 v = *(const uint2*)(Cs + r * 136 + col4);
        __half* dst = C + (size_t)(bm + r) * KL + k;
        if (k >= 0) {
            if ((k & 1) == 0) {
                *(uint32_t*)(dst)     = v.x;
                *(uint32_t*)(dst + 2) = v.y;
            } else {
                __half2 h0 = *(__half2*)&v.x;
                __half2 h1 = *(__half2*)&v.y;
                dst[0] = __low2half(h0);
                *(__half2*)(dst + 1) = __halves2half2(__high2half(h0), __low2half(h1));
                dst[3] = __high2half(h1);
            }
        } else if (k > -4) {
            __half tmp[4];
            *(uint2*)tmp = v;
#pragma unroll
            for (int e = 0; e < 4; e++)
                if (k + e >= 0) dst[e] = tmp[e];
        }
    }
}

// ---------------------------------------------------------------------------
// Wo GEMM (4-stage, fp32 out). Grid (8, 16, 1).
// ---------------------------------------------------------------------------
__global__ void __launch_bounds__(256)
wo_kernel(float* __restrict__ out) {
    constexpr int BM = 128, BN = 128, WM = 64, WN = 32;
    constexpr int MFRAG = WM / 16, NFRAG = WN / 8;

    const int bm = blockIdx.y * BM;
    const int bn = blockIdx.x * BN;

    extern __shared__ __half smh[];
    __half* As = smh;
    __half* Bs = smh + 4 * BM * G_LDSS;
    const uint32_t sA_base = smem_to_u32(As);
    const uint32_t sB_base = smem_to_u32(Bs);

    const int tid = threadIdx.x;
    const int lane = tid & 31;
    const int warp = tid >> 5;
    const int wm = warp & 1;
    const int wn = warp >> 1;
    const __half* Ag = g_ctxh + (size_t)bm * UU;
    const __half* Bg = g_woTh + (size_t)bn * UU;
    const int nIter = UU / G_KC;

    auto load_stage = [&](int stage, int buf) {
#pragma unroll
        for (int i = 0; i < 2; i++) {
            int idx = tid + i * 256;
            int row = idx >> 2, ch = idx & 3;
            cp_async16(sA_base + (uint32_t)(buf * BM * G_LDSS + row * G_LDSS + ch * 8) * 2u,
                       Ag + (size_t)row * UU + stage * G_KC + ch * 8);
        }
#pragma unroll
        for (int i = 0; i < 2; i++) {
            int idx = tid + i * 256;
            int row = idx >> 2, ch = idx & 3;
            cp_async16(sB_base + (uint32_t)(buf * BN * G_LDSS + row * G_LDSS + ch * 8) * 2u,
                       Bg + (size_t)row * UU + stage * G_KC + ch * 8);
        }
    };

    float acc[MFRAG][NFRAG][4];
#pragma unroll
    for (int i = 0; i < MFRAG; i++)
#pragma unroll
        for (int j = 0; j < NFRAG; j++)
#pragma unroll
            for (int v = 0; v < 4; v++) acc[i][j][v] = 0.0f;

    load_stage(0, 0); CP_COMMIT();
    load_stage(1, 1); CP_COMMIT();
    load_stage(2, 2); CP_COMMIT();

    const uint32_t aOff = (uint32_t)((wm * WM + (lane & 15)) * G_LDSS + (lane >> 4) * 8);
    const uint32_t bOff = (uint32_t)((wn * WN + (lane & 7) + (lane >> 4) * 8) * G_LDSS +
                                     ((lane >> 3) & 1) * 8);
    const int r4 = lane >> 2;
    const int c4 = lane & 3;

    for (int it = 0; it < nIter; ++it) {
        CP_WAIT2();
        __syncthreads();
        if (it + 3 < nIter) load_stage(it + 3, (it + 3) & 3);
        CP_COMMIT();

        const uint32_t aBuf = sA_base + (uint32_t)((it & 3) * BM * G_LDSS) * 2u;
        const uint32_t bBuf = sB_base + (uint32_t)((it & 3) * BN * G_LDSS) * 2u;

#pragma unroll
        for (int ks = 0; ks < 2; ks++) {
            uint32_t af[MFRAG][4];
            uint32_t bf[NFRAG][2];
#pragma unroll
            for (int fm = 0; fm < MFRAG; fm++)
                ldsm_x4(af[fm], aBuf + (aOff + fm * 16 * G_LDSS + ks * 16) * 2u);
#pragma unroll
            for (int fp = 0; fp < NFRAG / 2; fp++) {
                uint32_t r[4];
                ldsm_x4(r, bBuf + (bOff + fp * 16 * G_LDSS + ks * 16) * 2u);
                bf[2 * fp][0] = r[0]; bf[2 * fp][1] = r[1];
                bf[2 * fp + 1][0] = r[2]; bf[2 * fp + 1][1] = r[3];
            }
#pragma unroll
            for (int fm = 0; fm < MFRAG; fm++)
#pragma unroll
                for (int fn = 0; fn < NFRAG; fn++)
                    mma_f16(acc[fm][fn], af[fm], bf[fn]);
        }
    }

    const int m0 = bm + wm * WM;
    const int n0 = bn + wn * WN;
#pragma unroll
    for (int fm = 0; fm < MFRAG; fm++) {
#pragma unroll
        for (int fn = 0; fn < NFRAG; fn++) {
            int r = m0 + fm * 16 + r4;
            int cidx = n0 + fn * 8 + c4 * 2;
            *(float2*)(out + (size_t)r * UU + cidx) =
                make_float2(acc[fm][fn][0], acc[fm][fn][1]);
            *(float2*)(out + (size_t)(r + 8) * UU + cidx) =
                make_float2(acc[fm][fn][2], acc[fm][fn][3]);
        }
    }
}

// ---------------------------------------------------------------------------
// Split-K fused fp16 flash attention. P stays in registers: the Sc accumulator
// C-fragment layout IS the A-fragment layout for P@V (rows r4/r4+8, col pairs
// 2c4 / +8), so packed exp values feed mma directly.
// Grid (8*KSPLIT, H, B), 256 threads, 2 CTAs/SM.
// ---------------------------------------------------------------------------
__global__ void __launch_bounds__(256, 2) flash_kernel() {
    extern __shared__ __half smh[];
    __half* sQ  = smh;                  // [128][72]
    __half* sKa = sQ  + 128 * 72;
    __half* sKb = sKa + 128 * 72;
    __half* sV  = sKb + 128 * 72;       // [128 t][72 d]
    __half* sP  = sV  + 128 * 72;       // [128][136]  Sr staging
    const uint32_t uQ  = smem_to_u32(sQ);
    const uint32_t uKa = smem_to_u32(sKa);
    const uint32_t uKb = smem_to_u32(sKb);
    const uint32_t uV  = smem_to_u32(sV);
    const uint32_t uP  = smem_to_u32(sP);

    const int tid = threadIdx.x, lane = tid & 31, warp = tid >> 5;
    const int r4 = lane >> 2, c4 = lane & 3;
    const int qs = (int)blockIdx.x;
    const int qt = 7 - (qs / KSPLIT);
    const int split = qs % KSPLIT;
    const int h = blockIdx.y, b = blockIdx.z;
    const int q0 = qt * 128;
    const int nT = 9 + qt;
    const int t0 = (split * nT) / KSPLIT;
    const int t1 = ((split + 1) * nT) / KSPLIT;

    const __half* gQ = g_qch + ((size_t)b * QQ + q0) * UU + h * 64;
    const __half* gK = g_kh  + (size_t)b * KL * UU + h * 64;
    const __half* gV = g_vh  + (size_t)b * KL * UU + h * 64;
    const __half* gS = g_srh + (((size_t)b * HH + h) * QQ + q0) * KL;

    auto load_k = [&](int t, uint32_t dK) {
        const __half* src = gK + (size_t)t * 128 * UU;
        int i = tid;
#pragma unroll
        for (int rep = 0; rep < 4; rep++, i += 256) {
            int r = i >> 3, c = i & 7;
            cp_async16(dK + (uint32_t)(r * 72 + c * 8) * 2u, src + (size_t)r * UU + c * 8);
        }
    };
    auto load_v = [&](int t) {
        const __half* src = gV + (size_t)t * 128 * UU;
        int i = tid;
#pragma unroll
        for (int rep = 0; rep < 4; rep++, i += 256) {
            int r = i >> 3, c = i & 7;
            cp_async16(uV + (uint32_t)(r * 72 + c * 8) * 2u, src + (size_t)r * UU + c * 8);
        }
    };
    auto load_sr = [&](int t) {
        const __half* src = gS + (size_t)t * 128;
        int i = tid;
#pragma unroll
        for (int rep = 0; rep < 8; rep++, i += 256) {
            int r = i >> 4, c = i & 15;
            cp_async16(uP + (uint32_t)(r * 136 + c * 8) * 2u, src + (size_t)r * KL + c * 8);
        }
    };

    {
        int i = tid;
#pragma unroll
        for (int rep = 0; rep < 4; rep++, i += 256) {
            int r = i >> 3, c = i & 7;
            cp_async16(uQ + (uint32_t)(r * 72 + c * 8) * 2u, gQ + (size_t)r * UU + c * 8);
        }
        load_k(t0, uKa);
        CP_COMMIT();
        load_sr(t0);
        load_v(t0);
        CP_COMMIT();
    }

    const int lr0 = warp * 16 + r4;
    const int qg0 = q0 + lr0, qg1 = qg0 + 8;

    const uint32_t aOffQ = (uint32_t)((warp * 16 + (lane & 15)) * 72 + (lane >> 4) * 8);
    const uint32_t bOffK = (uint32_t)(((lane & 7) + (lane >> 4) * 8) * 72 + ((lane >> 3) & 1) * 8);
    const uint32_t bOffV = (uint32_t)((lane & 15) * 72 + (lane >> 4) * 8);

    float m0 = -1e30f, m1 = -1e30f, l0 = 0.f, l1 = 0.f;
    float accO[8][4];
#pragma unroll
    for (int f = 0; f < 8; f++)
#pragma unroll
        for (int v = 0; v < 4; v++) accO[f][v] = 0.f;

    for (int it = t0; it < t1; ++it) {
        const int li = it - t0;
        const uint32_t uK = (li & 1) ? uKb : uKa;
        CP_WAIT1();
        __syncthreads();

        // ---- phase 1: Sc = Qc @ K^T ----
        float accS[16][4];
#pragma unroll
        for (int f = 0; f < 16; f++)
#pragma unroll
            for (int v = 0; v < 4; v++) accS[f][v] = 0.f;
#pragma unroll
        for (int ks = 0; ks < 4; ks++) {
            uint32_t a[4];
            ldsm_x4(a, uQ + (aOffQ + ks * 16) * 2u);
#pragma unroll
            for (int fp = 0; fp < 8; fp++) {
                uint32_t r[4];
                ldsm_x4(r, uK + (bOffK + fp * 16 * 72 + ks * 16) * 2u);
                uint32_t b0[2] = {r[0], r[1]};
                uint32_t b1[2] = {r[2], r[3]};
                mma_f16(accS[2 * fp], a, b0);
                mma_f16(accS[2 * fp + 1], a, b1);
            }
        }

        // ---- prefetch next K ----
        {
            int kn = (it + 1 < t1) ? (it + 1) : (t1 - 1);
            load_k(kn, ((li + 1) & 1) ? uKb : uKa);
            CP_COMMIT();
        }

        CP_WAIT1();            // Sr(it) + V(it) ready
        __syncthreads();

        // ---- add staged shifted Sr, scale, mask; online softmax ----
        const int k0 = it * 128;
        const bool lastT = (it == nT - 1);
        const int lim0 = MEMN + qg0 - k0;
        const int lim1 = lim0 + 8;

        const __half* p0 = sP + lr0 * 136;
        const __half* p1 = p0 + 8 * 136;

        float rm0 = -1e30f, rm1 = -1e30f;
#pragma unroll
        for (int fn = 0; fn < 16; fn++) {
            int kc = fn * 8 + 2 * c4;
            float2 f0 = __half22float2(*(const __half2*)(p0 + kc));
            float2 f1 = __half22float2(*(const __half2*)(p1 + kc));
            float s0, s1, s2, s3;
            s0 = (!lastT || kc     <= lim0) ? (accS[fn][0] + f0.x) * 0.125f : -1e30f;
            s1 = (!lastT || kc + 1 <= lim0) ? (accS[fn][1] + f0.y) * 0.125f : -1e30f;
            s2 = (!lastT || kc     <= lim1) ? (accS[fn][2] + f1.x) * 0.125f : -1e30f;
            s3 = (!lastT || kc + 1 <= lim1) ? (accS[fn][3] + f1.y) * 0.125f : -1e30f;
            accS[fn][0] = s0; accS[fn][1] = s1; accS[fn][2] = s2; accS[fn][3] = s3;
            rm0 = fmaxf(rm0, fmaxf(s0, s1));
            rm1 = fmaxf(rm1, fmaxf(s2, s3));
        }
        rm0 = fmaxf(rm0, __shfl_xor_sync(~0u, rm0, 1));
        rm0 = fmaxf(rm0, __shfl_xor_sync(~0u, rm0, 2));
        rm1 = fmaxf(rm1, __shfl_xor_sync(~0u, rm1, 1));
        rm1 = fmaxf(rm1, __shfl_xor_sync(~0u, rm1, 2));
        float mN0 = fmaxf(m0, rm0), mN1 = fmaxf(m1, rm1);
        float al0 = __expf(m0 - mN0), al1 = __expf(m1 - mN1);
        m0 = mN0; m1 = mN1;

        // exp + pack P into accS[fn][0]=rows(r4), accS[fn][1]=rows(r4+8)
        float ps0 = 0.f, ps1 = 0.f;
#pragma unroll
        for (int fn = 0; fn < 16; fn++) {
            float e0 = __expf(accS[fn][0] - m0);
            float e1 = __expf(accS[fn][1] - m0);
            float e2 = __expf(accS[fn][2] - m1);
            float e3 = __expf(accS[fn][3] - m1);
            ps0 += e0 + e1; ps1 += e2 + e3;
            __half2 hp0 = __floats2half2_rn(e0, e1);
            __half2 hp1 = __floats2half2_rn(e2, e3);
            accS[fn][0] = __uint_as_float(*(uint32_t*)&hp0);
            accS[fn][1] = __uint_as_float(*(uint32_t*)&hp1);
        }
        ps0 += __shfl_xor_sync(~0u, ps0, 1); ps0 += __shfl_xor_sync(~0u, ps0, 2);
        ps1 += __shfl_xor_sync(~0u, ps1, 1); ps1 += __shfl_xor_sync(~0u, ps1, 2);
        l0 = l0 * al0 + ps0;
        l1 = l1 * al1 + ps1;
#pragma unroll
        for (int f = 0; f < 8; f++) {
            accO[f][0] *= al0; accO[f][1] *= al0;
            accO[f][2] *= al1; accO[f][3] *= al1;
        }

        // ---- phase 2: O += P @ V  (P from registers, V via ldmatrix.trans) ----
#pragma unroll
        for (int ks = 0; ks < 8; ks++) {
            uint32_t a[4] = {__float_as_uint(accS[2 * ks][0]),
                             __float_as_uint(accS[2 * ks][1]),
                             __float_as_uint(accS[2 * ks + 1][0]),
                             __float_as_uint(accS[2 * ks + 1][1])};
#pragma unroll
            for (int fp = 0; fp < 4; fp++) {
                uint32_t r[4];
                ldsm_x4t(r, uV + (bOffV + ks * 16 * 72 + fp * 16) * 2u);
                uint32_t b0[2] = {r[0], r[1]};
                uint32_t b1[2] = {r[2], r[3]};
                mma_f16(accO[2 * fp], a, b0);
                mma_f16(accO[2 * fp + 1], a, b1);
            }
        }
        __syncthreads();       // everyone done with sP / sV

        // ---- prefetch next Sr + V ----
        {
            int vn = (it + 1 < t1) ? (it + 1) : (t1 - 1);
            load_sr(vn);
            load_v(vn);
            CP_COMMIT();
        }
    }

    const size_t base0 = ((size_t)b * HH + h) * QQ + qg0;
    const size_t base1 = base0 + 8;
    float* o0 = g_opart + (base0 * KSPLIT + split) * DHH;
    float* o1 = g_opart + (base1 * KSPLIT + split) * DHH;
#pragma unroll
    for (int fn = 0; fn < 8; fn++) {
        int col = fn * 8 + 2 * c4;
        *(float2*)(o0 + col) = make_float2(accO[fn][0], accO[fn][1]);
        *(float2*)(o1 + col) = make_float2(accO[fn][2], accO[fn][3]);
    }
    if (c4 == 0) {
        float* ml0 = g_ml + (base0 * KSPLIT + split) * 2;
        float* ml1 = g_ml + (base1 * KSPLIT + split) * 2;
        ml0[0] = m0; ml0[1] = l0;
        ml1[0] = m1; ml1[1] = l1;
    }
}

// ---------------------------------------------------------------------------
// Combine split-K partials -> ctx (fp16)
// ---------------------------------------------------------------------------
__global__ void __launch_bounds__(256) combine_kernel() {
    const int col = threadIdx.x & 63;
    const int rloc = threadIdx.x >> 6;
    const int q = blockIdx.x * 4 + rloc;
    const int h = blockIdx.y, b = blockIdx.z;
    const size_t base = ((size_t)b * HH + h) * QQ + q;

    float m[KSPLIT], l[KSPLIT];
#pragma unroll
    for (int s = 0; s < KSPLIT; s++) {
        m[s] = g_ml[(base * KSPLIT + s) * 2 + 0];
        l[s] = g_ml[(base * KSPLIT + s) * 2 + 1];
    }
    float mx = m[0];
#pragma unroll
    for (int s = 1; s < KSPLIT; s++) mx = fmaxf(mx, m[s]);
    float w[KSPLIT], L = 0.f;
#pragma unroll
    for (int s = 0; s < KSPLIT; s++) { w[s] = __expf(m[s] - mx); L += l[s] * w[s]; }
    const float inv = 1.0f / L;

    float o = 0.f;
#pragma unroll
    for (int s = 0; s < KSPLIT; s++)
        o += g_opart[(base * KSPLIT + s) * DHH + col] * w[s];
    g_ctxh[((size_t)b * QQ + q) * UU + h * 64 + col] = __float2half(o * inv);
}

// ---------------------------------------------------------------------------
// Launch
// ---------------------------------------------------------------------------
extern "C" void kernel_launch(void* const* d_in, const int* in_sizes, int n_in,
                              void* d_out, int out_size) {
    const float* inputs    = (const float*)d_in[0];
    const float* relatives = (const float*)d_in[1];
    const float* memories  = (const float*)d_in[2];
    const float* bias_c    = (const float*)d_in[3];
    const float* bias_r    = (const float*)d_in[4];
    const float* Wq        = (const float*)d_in[5];
    const float* Wkv       = (const float*)d_in[6];
    const float* Wr        = (const float*)d_in[7];
    const float* Wo        = (const float*)d_in[8];
    float* out             = (float*)d_out;

    constexpr int SMEM_G  = 4 * (128 + 128) * G_LDSS * 2;                // 81920
    constexpr int SMEM_SR = 2 * (128 + 128) * G_LDSS * 2;                // 40960
    constexpr int SMEM_F  = (3 * 128 * 72 + 128 * 72 + 128 * 136) * 2;   // 108544
    cudaFuncSetAttribute((const void*)proj_kernel,
                         cudaFuncAttributeMaxDynamicSharedMemorySize, SMEM_G);
    cudaFuncSetAttribute((const void*)wo_kernel,
                         cudaFuncAttributeMaxDynamicSharedMemorySize, SMEM_G);
    cudaFuncSetAttribute((const void*)sr_kernel,
                         cudaFuncAttributeMaxDynamicSharedMemorySize, SMEM_SR);
    cudaFuncSetAttribute((const void*)flash_kernel,
                         cudaFuncAttributeMaxDynamicSharedMemorySize, SMEM_F);

    // 0. all weight transposes in one launch
    wtrans_kernel<<<5120, dim3(32, 8)>>>(Wq, Wkv, Wr, Wo);

    // 1. fullh = fp16(concat); relrh = fp16(relatives)
    {
        size_t total4 = (size_t)BB * KL * UU / 4;
        prep_kernel<<<(unsigned)((2 * total4 + 255) / 256), 256>>>(memories, inputs, relatives);
    }

    // 2. merged projections: wkv | wr | wq  (896 CTAs, one launch)
    proj_kernel<<<896, 256, SMEM_G>>>(bias_c, bias_r);

    // 3. SrShift = shifted (qr @ wr^T), SMEM-staged vectorized store
    sr_kernel<<<dim3(KL / 128, QQ / 128, BB * HH), 256, SMEM_SR>>>();

    // 4. split-K fused fp16 flash -> partials
    flash_kernel<<<dim3(8 * KSPLIT, HH, BB), 256, SMEM_F>>>();

    // 5. combine partials -> ctx (fp16)
    combine_kernel<<<dim3(QQ / 4, HH, BB), 256>>>();

    // 6. out = ctx @ Wo (fp32 out)
    wo_kernel<<<dim3(UU / 128, (BB * QQ) / 128, 1), 256, SMEM_G>>>(out);
}

// round 14
// speedup vs baseline: 1.4743x; 1.4743x over previous
#include <cuda_runtime.h>
#include <cuda_fp16.h>
#include <cstdint>

// Problem constants
#define BB   2
#define QQ   1024
#define MEMN 1024
#define UU   1024
#define HH   16
#define DHH  64
#define KL   2048   // MEM + Q
#define KSPLIT 3

// ---------------------------------------------------------------------------
// Scratch (allocation-free: __device__ globals, 16B-aligned for cp.async)
// ---------------------------------------------------------------------------
__device__ __align__(16) __half g_fullh[(size_t)BB * KL * UU];     // fp16 concat
__device__ __align__(16) __half g_relrh[(size_t)BB * KL * UU];     // fp16 relatives
__device__ __align__(16) __half g_qch [(size_t)BB * QQ * UU];      // fp16 q + bias_c
__device__ __align__(16) __half g_qrh [(size_t)BB * QQ * UU];      // fp16 q + bias_r
__device__ __align__(16) __half g_kh  [(size_t)BB * KL * UU];      // fp16 K
__device__ __align__(16) __half g_vh  [(size_t)BB * KL * UU];      // fp16 V  [b,t,u]
__device__ __align__(16) __half g_wrh [(size_t)BB * KL * UU];      // fp16 w_r
__device__ __align__(16) __half g_srh [(size_t)BB * HH * QQ * KL]; // fp16 Sr SHIFTED
__device__ __align__(16) __half g_ctxh[(size_t)BB * QQ * UU];      // fp16 attention out
__device__ __align__(16) __half g_wqTh [(size_t)UU * UU];
__device__ __align__(16) __half g_wkvTh[(size_t)2 * UU * UU];
__device__ __align__(16) __half g_wrTh [(size_t)UU * UU];
__device__ __align__(16) __half g_woTh [(size_t)UU * UU];
__device__ float g_opart[(size_t)BB * HH * QQ * KSPLIT * DHH];
__device__ float g_ml   [(size_t)BB * HH * QQ * KSPLIT * 2];

// ---------------------------------------------------------------------------
// Helpers
// ---------------------------------------------------------------------------
__device__ __forceinline__ uint32_t smem_to_u32(const void* p) {
    uint32_t a;
    asm("{ .reg .u64 t; cvta.to.shared.u64 t, %1; cvt.u32.u64 %0, t; }" : "=r"(a) : "l"(p));
    return a;
}
__device__ __forceinline__ void cp_async16(uint32_t saddr, const void* gaddr) {
    asm volatile("cp.async.cg.shared.global [%0], [%1], 16;" :: "r"(saddr), "l"(gaddr));
}
#define CP_COMMIT() asm volatile("cp.async.commit_group;" ::: "memory")
#define CP_WAIT0()  asm volatile("cp.async.wait_group 0;" ::: "memory")
#define CP_WAIT1()  asm volatile("cp.async.wait_group 1;" ::: "memory")
#define CP_WAIT2()  asm volatile("cp.async.wait_group 2;" ::: "memory")

__device__ __forceinline__ void mma_f16(float acc[4], const uint32_t a[4], const uint32_t b[2]) {
    asm volatile("mma.sync.aligned.m16n8k16.row.col.f32.f16.f16.f32 "
        "{%0,%1,%2,%3}, {%4,%5,%6,%7}, {%8,%9}, {%0,%1,%2,%3};"
        : "+f"(acc[0]), "+f"(acc[1]), "+f"(acc[2]), "+f"(acc[3])
        : "r"(a[0]), "r"(a[1]), "r"(a[2]), "r"(a[3]), "r"(b[0]), "r"(b[1]));
}
__device__ __forceinline__ void ldsm_x4(uint32_t* r, uint32_t addr) {
    asm volatile("ldmatrix.sync.aligned.m8n8.x4.shared.b16 {%0,%1,%2,%3}, [%4];"
        : "=r"(r[0]), "=r"(r[1]), "=r"(r[2]), "=r"(r[3]) : "r"(addr));
}
__device__ __forceinline__ void ldsm_x4t(uint32_t* r, uint32_t addr) {
    asm volatile("ldmatrix.sync.aligned.m8n8.x4.trans.shared.b16 {%0,%1,%2,%3}, [%4];"
        : "=r"(r[0]), "=r"(r[1]), "=r"(r[2]), "=r"(r[3]) : "r"(addr));
}

// ---------------------------------------------------------------------------
// prep: concat(memories, inputs) -> g_fullh ; relatives -> g_relrh (fp16)
// ---------------------------------------------------------------------------
__global__ void prep_kernel(const float* __restrict__ mem,
                            const float* __restrict__ inp,
                            const float* __restrict__ rel) {
    const size_t total4 = (size_t)BB * KL * UU / 4;
    size_t i = (size_t)blockIdx.x * blockDim.x + threadIdx.x;
    if (i < total4) {
        size_t elem = i * 4;
        int b = (int)(elem / ((size_t)KL * UU));
        size_t rem = elem % ((size_t)KL * UU);
        int t = (int)(rem / UU);
        int u = (int)(rem % UU);
        float4 v;
        if (t < MEMN) v = *(const float4*)(mem + ((size_t)b * MEMN + t) * UU + u);
        else          v = *(const float4*)(inp + ((size_t)b * QQ + (t - MEMN)) * UU + u);
        __half2* o = (__half2*)(g_fullh + elem);
        o[0] = __floats2half2_rn(v.x, v.y);
        o[1] = __floats2half2_rn(v.z, v.w);
    } else if (i < 2 * total4) {
        size_t j = i - total4;
        float4 v = ((const float4*)rel)[j];
        __half2* o = (__half2*)(g_relrh + j * 4);
        o[0] = __floats2half2_rn(v.x, v.y);
        o[1] = __floats2half2_rn(v.z, v.w);
    }
}

// ---------------------------------------------------------------------------
// Fused weight transposes: W[K=1024, N] row-major -> W^T[N, 1024] fp16
// ---------------------------------------------------------------------------
__global__ void wtrans_kernel(const float* __restrict__ Wq, const float* __restrict__ Wkv,
                              const float* __restrict__ Wr, const float* __restrict__ Wo) {
    __shared__ float t[32][33];
    int bid = blockIdx.x;
    const float* in; __half* out; int cols;
    if (bid < 1024)      { in = Wq;  out = g_wqTh;  cols = 1024; }
    else if (bid < 3072) { in = Wkv; out = g_wkvTh; cols = 2048; bid -= 1024; }
    else if (bid < 4096) { in = Wr;  out = g_wrTh;  cols = 1024; bid -= 3072; }
    else                 { in = Wo;  out = g_woTh;  cols = 1024; bid -= 4096; }
    int tilesX = cols / 32;
    int c0 = (bid % tilesX) * 32;
    int r0 = (bid / tilesX) * 32;
    int tx = threadIdx.x, ty = threadIdx.y;
#pragma unroll
    for (int i = 0; i < 32; i += 8)
        t[ty + i][tx] = in[(size_t)(r0 + ty + i) * cols + c0 + tx];
    __syncthreads();
#pragma unroll
    for (int i = 0; i < 32; i += 8)
        out[(size_t)(c0 + ty + i) * 1024 + r0 + tx] = __float2half(t[tx][ty + i]);
}

// ===========================================================================
// Shared GEMM constants (BM=BN=128, WM=64, WN=32, KC=32)
// ===========================================================================
#define G_LDSS 40
#define G_KC   32

// ---------------------------------------------------------------------------
// Merged projection GEMM: one launch covers wkv (EPI4), wr (EPI3), wq (EPI2).
// Flat grid: [0,512) wkv | [512,768) wr | [768,896) wq. 4-stage pipeline.
// ---------------------------------------------------------------------------
__global__ void __launch_bounds__(256)
proj_kernel(const float* __restrict__ bc, const float* __restrict__ br) {
    constexpr int BM = 128, BN = 128, WM = 64, WN = 32;
    constexpr int MFRAG = WM / 16, NFRAG = WN / 8;

    int cta = blockIdx.x;
    int epi;
    const __half* A;
    const __half* Bw;
    __half *Ch = nullptr, *C2h = nullptr;
    int bm, bn;
    if (cta < 512) {               // wkv
        epi = 4;
        int bx = cta & 15, by = cta >> 4;
        A = g_fullh; Bw = g_wkvTh;
        Ch = g_vh; C2h = g_kh;
        bm = by * BM; bn = bx * BN;
    } else if (cta < 768) {        // wr
        epi = 3;
        int c = cta - 512;
        int bx = c & 7, by = c >> 3;
        A = g_relrh; Bw = g_wrTh;
        Ch = g_wrh;
        bm = by * BM; bn = bx * BN;
    } else {                       // wq
        epi = 2;
        int c = cta - 768;
        int bx = c & 7, by = (c >> 3) & 7, zz = c >> 6;
        A = g_fullh + (size_t)MEMN * UU + (size_t)zz * KL * UU;
        Bw = g_wqTh;
        Ch = g_qch + (size_t)zz * QQ * UU;
        C2h = g_qrh + (size_t)zz * QQ * UU;
        bm = by * BM; bn = bx * BN;
    }
    const int lda = UU, ldb = UU, ldc = UU;
    const int nIter = UU / G_KC;   // 32

    extern __shared__ __half smh[];
    __half* As = smh;
    __half* Bs = smh + 4 * BM * G_LDSS;
    const uint32_t sA_base = smem_to_u32(As);
    const uint32_t sB_base = smem_to_u32(Bs);

    const int tid = threadIdx.x;
    const int lane = tid & 31;
    const int warp = tid >> 5;
    const int wm = warp & 1;
    const int wn = warp >> 1;
    const __half* Ag = A + (size_t)bm * lda;
    const __half* Bg = Bw + (size_t)bn * ldb;

    auto load_stage = [&](int stage, int buf) {
#pragma unroll
        for (int i = 0; i < 2; i++) {
            int idx = tid + i * 256;
            int row = idx >> 2, ch = idx & 3;
            uint32_t s = sA_base + (uint32_t)(buf * BM * G_LDSS + row * G_LDSS + ch * 8) * 2u;
            cp_async16(s, Ag + (size_t)row * lda + stage * G_KC + ch * 8);
        }
#pragma unroll
        for (int i = 0; i < 2; i++) {
            int idx = tid + i * 256;
            int row = idx >> 2, ch = idx & 3;
            uint32_t s = sB_base + (uint32_t)(buf * BN * G_LDSS + row * G_LDSS + ch * 8) * 2u;
            cp_async16(s, Bg + (size_t)row * ldb + stage * G_KC + ch * 8);
        }
    };

    float acc[MFRAG][NFRAG][4];
#pragma unroll
    for (int i = 0; i < MFRAG; i++)
#pragma unroll
        for (int j = 0; j < NFRAG; j++)
#pragma unroll
            for (int v = 0; v < 4; v++) acc[i][j][v] = 0.0f;

    load_stage(0, 0); CP_COMMIT();
    load_stage(1, 1); CP_COMMIT();
    load_stage(2, 2); CP_COMMIT();

    const uint32_t aOff = (uint32_t)((wm * WM + (lane & 15)) * G_LDSS + (lane >> 4) * 8);
    const uint32_t bOff = (uint32_t)((wn * WN + (lane & 7) + (lane >> 4) * 8) * G_LDSS +
                                     ((lane >> 3) & 1) * 8);
    const int r4 = lane >> 2;
    const int c4 = lane & 3;

    for (int it = 0; it < nIter; ++it) {
        CP_WAIT2();
        __syncthreads();
        if (it + 3 < nIter) load_stage(it + 3, (it + 3) & 3);
        CP_COMMIT();

        const uint32_t aBuf = sA_base + (uint32_t)((it & 3) * BM * G_LDSS) * 2u;
        const uint32_t bBuf = sB_base + (uint32_t)((it & 3) * BN * G_LDSS) * 2u;

#pragma unroll
        for (int ks = 0; ks < 2; ks++) {
            uint32_t af[MFRAG][4];
            uint32_t bf[NFRAG][2];
#pragma unroll
            for (int fm = 0; fm < MFRAG; fm++)
                ldsm_x4(af[fm], aBuf + (aOff + fm * 16 * G_LDSS + ks * 16) * 2u);
#pragma unroll
            for (int fp = 0; fp < NFRAG / 2; fp++) {
                uint32_t r[4];
                ldsm_x4(r, bBuf + (bOff + fp * 16 * G_LDSS + ks * 16) * 2u);
                bf[2 * fp][0] = r[0]; bf[2 * fp][1] = r[1];
                bf[2 * fp + 1][0] = r[2]; bf[2 * fp + 1][1] = r[3];
            }
#pragma unroll
            for (int fm = 0; fm < MFRAG; fm++)
#pragma unroll
                for (int fn = 0; fn < NFRAG; fn++)
                    mma_f16(acc[fm][fn], af[fm], bf[fn]);
        }
    }

    const int m0 = bm + wm * WM;
    const int n0 = bn + wn * WN;
#pragma unroll
    for (int fm = 0; fm < MFRAG; fm++) {
#pragma unroll
        for (int fn = 0; fn < NFRAG; fn++) {
            int r = m0 + fm * 16 + r4;
            int cidx = n0 + fn * 8 + c4 * 2;
            float a0 = acc[fm][fn][0], a1 = acc[fm][fn][1];
            float a2 = acc[fm][fn][2], a3 = acc[fm][fn][3];
            if (epi == 4) {
                if (cidx < UU) {
                    *(__half2*)(C2h + (size_t)r * UU + cidx) = __floats2half2_rn(a0, a1);
                    *(__half2*)(C2h + (size_t)(r + 8) * UU + cidx) = __floats2half2_rn(a2, a3);
                } else {
                    *(__half2*)(Ch + (size_t)r * UU + cidx - UU) = __floats2half2_rn(a0, a1);
                    *(__half2*)(Ch + (size_t)(r + 8) * UU + cidx - UU) = __floats2half2_rn(a2, a3);
                }
            } else if (epi == 3) {
                *(__half2*)(Ch + (size_t)r * ldc + cidx) = __floats2half2_rn(a0, a1);
                *(__half2*)(Ch + (size_t)(r + 8) * ldc + cidx) = __floats2half2_rn(a2, a3);
            } else {  // epi == 2
                float b0 = bc[cidx], b1 = bc[cidx + 1];
                float r0 = br[cidx], r1 = br[cidx + 1];
                *(__half2*)(Ch + (size_t)r * ldc + cidx) = __floats2half2_rn(a0 + b0, a1 + b1);
                *(__half2*)(Ch + (size_t)(r + 8) * ldc + cidx) = __floats2half2_rn(a2 + b0, a3 + b1);
                *(__half2*)(C2h + (size_t)r * ldc + cidx) = __floats2half2_rn(a0 + r0, a1 + r1);
                *(__half2*)(C2h + (size_t)(r + 8) * ldc + cidx) = __floats2half2_rn(a2 + r0, a3 + r1);
            }
        }
    }
}

// ---------------------------------------------------------------------------
// Sr shifted GEMM, K=64 specialized: 2 flat K-chunks, SMEM-staged coalesced
// shifted store (R12 scalar store). __launch_bounds__(256,3) for 3 CTAs/SM.
// ---------------------------------------------------------------------------
__global__ void __launch_bounds__(256, 3)
sr_kernel() {
    constexpr int BM = 128, BN = 128, WM = 64, WN = 32;
    constexpr int MFRAG = WM / 16, NFRAG = WN / 8;

    const int bm = blockIdx.y * BM;
    const int bn = blockIdx.x * BN;
    if (bn + bm + BM + BN - 2 - (QQ - 1) < 0) return;  // fully below shift diagonal

    const int z = blockIdx.z;          // b*HH + h
    const int z1 = z / HH, z2 = z % HH;
    const __half* A = g_qrh + (size_t)z1 * QQ * UU + (size_t)z2 * 64;
    const __half* B = g_wrh + (size_t)z1 * KL * UU + (size_t)z2 * 64;
    __half* C = g_srh + (size_t)z * QQ * KL;

    extern __shared__ __half smh[];
    __half* As = smh;                       // [2][128][40]
    __half* Bs = smh + 2 * BM * G_LDSS;     // [2][128][40]
    const uint32_t sA_base = smem_to_u32(As);
    const uint32_t sB_base = smem_to_u32(Bs);

    const int tid = threadIdx.x;
    const int lane = tid & 31;
    const int warp = tid >> 5;
    const int wm = warp & 1;
    const int wn = warp >> 1;
    const __half* Ag = A + (size_t)bm * UU;
    const __half* Bg = B + (size_t)bn * UU;

    // load both K chunks
#pragma unroll
    for (int st = 0; st < 2; st++) {
#pragma unroll
        for (int i = 0; i < 2; i++) {
            int idx = tid + i * 256;
            int row = idx >> 2, ch = idx & 3;
            cp_async16(sA_base + (uint32_t)(st * BM * G_LDSS + row * G_LDSS + ch * 8) * 2u,
                       Ag + (size_t)row * UU + st * G_KC + ch * 8);
        }
#pragma unroll
        for (int i = 0; i < 2; i++) {
            int idx = tid + i * 256;
            int row = idx >> 2, ch = idx & 3;
            cp_async16(sB_base + (uint32_t)(st * BN * G_LDSS + row * G_LDSS + ch * 8) * 2u,
                       Bg + (size_t)row * UU + st * G_KC + ch * 8);
        }
        CP_COMMIT();
    }
    CP_WAIT0();
    __syncthreads();

    const uint32_t aOff = (uint32_t)((wm * WM + (lane & 15)) * G_LDSS + (lane >> 4) * 8);
    const uint32_t bOff = (uint32_t)((wn * WN + (lane & 7) + (lane >> 4) * 8) * G_LDSS +
                                     ((lane >> 3) & 1) * 8);
    const int r4 = lane >> 2;
    const int c4 = lane & 3;

    float acc[MFRAG][NFRAG][4];
#pragma unroll
    for (int i = 0; i < MFRAG; i++)
#pragma unroll
        for (int j = 0; j < NFRAG; j++)
#pragma unroll
            for (int v = 0; v < 4; v++) acc[i][j][v] = 0.0f;

#pragma unroll
    for (int st = 0; st < 2; st++) {
        const uint32_t aBuf = sA_base + (uint32_t)(st * BM * G_LDSS) * 2u;
        const uint32_t bBuf = sB_base + (uint32_t)(st * BN * G_LDSS) * 2u;
#pragma unroll
        for (int ks = 0; ks < 2; ks++) {
            uint32_t af[MFRAG][4];
            uint32_t bf[NFRAG][2];
#pragma unroll
            for (int fm = 0; fm < MFRAG; fm++)
                ldsm_x4(af[fm], aBuf + (aOff + fm * 16 * G_LDSS + ks * 16) * 2u);
#pragma unroll
            for (int fp = 0; fp < NFRAG / 2; fp++) {
                uint32_t r[4];
                ldsm_x4(r, bBuf + (bOff + fp * 16 * G_LDSS + ks * 16) * 2u);
                bf[2 * fp][0] = r[0]; bf[2 * fp][1] = r[1];
                bf[2 * fp + 1][0] = r[2]; bf[2 * fp + 1][1] = r[3];
            }
#pragma unroll
            for (int fm = 0; fm < MFRAG; fm++)
#pragma unroll
                for (int fn = 0; fn < NFRAG; fn++)
                    mma_f16(acc[fm][fn], af[fm], bf[fn]);
        }
    }

    // ---- stage C tile in SMEM [128][136] (reuse A/B buffers) ----
    __syncthreads();
    __half* Cs = smh;
    const int m0l = wm * WM;
    const int n0l = wn * WN;
#pragma unroll
    for (int fm = 0; fm < MFRAG; fm++) {
#pragma unroll
        for (int fn = 0; fn < NFRAG; fn++) {
            int lr = m0l + fm * 16 + r4;
            int lc = n0l + fn * 8 + 2 * c4;
            *(__half2*)(Cs + lr * 136 + lc) =
                __floats2half2_rn(acc[fm][fn][0], acc[fm][fn][1]);
            *(__half2*)(Cs + (lr + 8) * 136 + lc) =
                __floats2half2_rn(acc[fm][fn][2], acc[fm][fn][3]);
        }
    }
    __syncthreads();

    // ---- coalesced shifted store: 2 rows per pass, 128 threads per row ----
    const int col = tid & 127;
    const int off = bn - (QQ - 1) + bm;   // k of (row 0, col 0)
#pragma unroll 4
    for (int r = tid >> 7; r < 128; r += 2) {
        int k = off + r + col;            // k = bn + col - (Q-1) + (bm + r)
        if (k >= 0)
            C[(size_t)(bm + r) * KL + k] = Cs[r * 136 + col];
    }
}

// ---------------------------------------------------------------------------
// Wo GEMM (4-stage, fp32 out). Grid (8, 16, 1).
// ---------------------------------------------------------------------------
__global__ void __launch_bounds__(256)
wo_kernel(float* __restrict__ out) {
    constexpr int BM = 128, BN = 128, WM = 64, WN = 32;
    constexpr int MFRAG = WM / 16, NFRAG = WN / 8;

    const int bm = blockIdx.y * BM;
    const int bn = blockIdx.x * BN;

    extern __shared__ __half smh[];
    __half* As = smh;
    __half* Bs = smh + 4 * BM * G_LDSS;
    const uint32_t sA_base = smem_to_u32(As);
    const uint32_t sB_base = smem_to_u32(Bs);

    const int tid = threadIdx.x;
    const int lane = tid & 31;
    const int warp = tid >> 5;
    const int wm = warp & 1;
    const int wn = warp >> 1;
    const __half* Ag = g_ctxh + (size_t)bm * UU;
    const __half* Bg = g_woTh + (size_t)bn * UU;
    const int nIter = UU / G_KC;

    auto load_stage = [&](int stage, int buf) {
#pragma unroll
        for (int i = 0; i < 2; i++) {
            int idx = tid + i * 256;
            int row = idx >> 2, ch = idx & 3;
            cp_async16(sA_base + (uint32_t)(buf * BM * G_LDSS + row * G_LDSS + ch * 8) * 2u,
                       Ag + (size_t)row * UU + stage * G_KC + ch * 8);
        }
#pragma unroll
        for (int i = 0; i < 2; i++) {
            int idx = tid + i * 256;
            int row = idx >> 2, ch = idx & 3;
            cp_async16(sB_base + (uint32_t)(buf * BN * G_LDSS + row * G_LDSS + ch * 8) * 2u,
                       Bg + (size_t)row * UU + stage * G_KC + ch * 8);
        }
    };

    float acc[MFRAG][NFRAG][4];
#pragma unroll
    for (int i = 0; i < MFRAG; i++)
#pragma unroll
        for (int j = 0; j < NFRAG; j++)
#pragma unroll
            for (int v = 0; v < 4; v++) acc[i][j][v] = 0.0f;

    load_stage(0, 0); CP_COMMIT();
    load_stage(1, 1); CP_COMMIT();
    load_stage(2, 2); CP_COMMIT();

    const uint32_t aOff = (uint32_t)((wm * WM + (lane & 15)) * G_LDSS + (lane >> 4) * 8);
    const uint32_t bOff = (uint32_t)((wn * WN + (lane & 7) + (lane >> 4) * 8) * G_LDSS +
                                     ((lane >> 3) & 1) * 8);
    const int r4 = lane >> 2;
    const int c4 = lane & 3;

    for (int it = 0; it < nIter; ++it) {
        CP_WAIT2();
        __syncthreads();
        if (it + 3 < nIter) load_stage(it + 3, (it + 3) & 3);
        CP_COMMIT();

        const uint32_t aBuf = sA_base + (uint32_t)((it & 3) * BM * G_LDSS) * 2u;
        const uint32_t bBuf = sB_base + (uint32_t)((it & 3) * BN * G_LDSS) * 2u;

#pragma unroll
        for (int ks = 0; ks < 2; ks++) {
            uint32_t af[MFRAG][4];
            uint32_t bf[NFRAG][2];
#pragma unroll
            for (int fm = 0; fm < MFRAG; fm++)
                ldsm_x4(af[fm], aBuf + (aOff + fm * 16 * G_LDSS + ks * 16) * 2u);
#pragma unroll
            for (int fp = 0; fp < NFRAG / 2; fp++) {
                uint32_t r[4];
                ldsm_x4(r, bBuf + (bOff + fp * 16 * G_LDSS + ks * 16) * 2u);
                bf[2 * fp][0] = r[0]; bf[2 * fp][1] = r[1];
                bf[2 * fp + 1][0] = r[2]; bf[2 * fp + 1][1] = r[3];
            }
#pragma unroll
            for (int fm = 0; fm < MFRAG; fm++)
#pragma unroll
                for (int fn = 0; fn < NFRAG; fn++)
                    mma_f16(acc[fm][fn], af[fm], bf[fn]);
        }
    }

    const int m0 = bm + wm * WM;
    const int n0 = bn + wn * WN;
#pragma unroll
    for (int fm = 0; fm < MFRAG; fm++) {
#pragma unroll
        for (int fn = 0; fn < NFRAG; fn++) {
            int r = m0 + fm * 16 + r4;
            int cidx = n0 + fn * 8 + c4 * 2;
            *(float2*)(out + (size_t)r * UU + cidx) =
                make_float2(acc[fm][fn][0], acc[fm][fn][1]);
            *(float2*)(out + (size_t)(r + 8) * UU + cidx) =
                make_float2(acc[fm][fn][2], acc[fm][fn][3]);
        }
    }
}

// ---------------------------------------------------------------------------
// Split-K fused fp16 flash attention (R12 version: P through SMEM).
// Grid (8*KSPLIT, H, B), 256 threads, 2 CTAs/SM.
// ---------------------------------------------------------------------------
__global__ void __launch_bounds__(256, 2) flash_kernel() {
    extern __shared__ __half smh[];
    __half* sQ  = smh;                  // [128][72]
    __half* sKa = sQ  + 128 * 72;
    __half* sKb = sKa + 128 * 72;
    __half* sV  = sKb + 128 * 72;       // [128 t][72 d]
    __half* sP  = sV  + 128 * 72;       // [128][136]
    const uint32_t uQ  = smem_to_u32(sQ);
    const uint32_t uKa = smem_to_u32(sKa);
    const uint32_t uKb = smem_to_u32(sKb);
    const uint32_t uV  = smem_to_u32(sV);
    const uint32_t uP  = smem_to_u32(sP);

    const int tid = threadIdx.x, lane = tid & 31, warp = tid >> 5;
    const int r4 = lane >> 2, c4 = lane & 3;
    const int qs = (int)blockIdx.x;
    const int qt = 7 - (qs / KSPLIT);
    const int split = qs % KSPLIT;
    const int h = blockIdx.y, b = blockIdx.z;
    const int q0 = qt * 128;
    const int nT = 9 + qt;
    const int t0 = (split * nT) / KSPLIT;
    const int t1 = ((split + 1) * nT) / KSPLIT;

    const __half* gQ = g_qch + ((size_t)b * QQ + q0) * UU + h * 64;
    const __half* gK = g_kh  + (size_t)b * KL * UU + h * 64;
    const __half* gV = g_vh  + (size_t)b * KL * UU + h * 64;
    const __half* gS = g_srh + (((size_t)b * HH + h) * QQ + q0) * KL;

    auto load_k = [&](int t, uint32_t dK) {
        const __half* src = gK + (size_t)t * 128 * UU;
        int i = tid;
#pragma unroll
        for (int rep = 0; rep < 4; rep++, i += 256) {
            int r = i >> 3, c = i & 7;
            cp_async16(dK + (uint32_t)(r * 72 + c * 8) * 2u, src + (size_t)r * UU + c * 8);
        }
    };
    auto load_v = [&](int t) {
        const __half* src = gV + (size_t)t * 128 * UU;
        int i = tid;
#pragma unroll
        for (int rep = 0; rep < 4; rep++, i += 256) {
            int r = i >> 3, c = i & 7;
            cp_async16(uV + (uint32_t)(r * 72 + c * 8) * 2u, src + (size_t)r * UU + c * 8);
        }
    };
    auto load_sr = [&](int t) {
        const __half* src = gS + (size_t)t * 128;
        int i = tid;
#pragma unroll
        for (int rep = 0; rep < 8; rep++, i += 256) {
            int r = i >> 4, c = i & 15;
            cp_async16(uP + (uint32_t)(r * 136 + c * 8) * 2u, src + (size_t)r * KL + c * 8);
        }
    };

    {
        int i = tid;
#pragma unroll
        for (int rep = 0; rep < 4; rep++, i += 256) {
            int r = i >> 3, c = i & 7;
            cp_async16(uQ + (uint32_t)(r * 72 + c * 8) * 2u, gQ + (size_t)r * UU + c * 8);
        }
        load_k(t0, uKa);
        CP_COMMIT();
        load_sr(t0);
        load_v(t0);
        CP_COMMIT();
    }

    const int lr0 = warp * 16 + r4;
    const int qg0 = q0 + lr0, qg1 = qg0 + 8;

    const uint32_t aOffQ = (uint32_t)((warp * 16 + (lane & 15)) * 72 + (lane >> 4) * 8);
    const uint32_t aOffP = (uint32_t)((warp * 16 + (lane & 15)) * 136 + (lane >> 4) * 8);
    const uint32_t bOffK = (uint32_t)(((lane & 7) + (lane >> 4) * 8) * 72 + ((lane >> 3) & 1) * 8);
    const uint32_t bOffV = (uint32_t)((lane & 15) * 72 + (lane >> 4) * 8);

    float m0 = -1e30f, m1 = -1e30f, l0 = 0.f, l1 = 0.f;
    float accO[8][4];
#pragma unroll
    for (int f = 0; f < 8; f++)
#pragma unroll
        for (int v = 0; v < 4; v++) accO[f][v] = 0.f;

    for (int it = t0; it < t1; ++it) {
        const int li = it - t0;
        const uint32_t uK = (li & 1) ? uKb : uKa;
        CP_WAIT1();
        __syncthreads();

        float accS[16][4];
#pragma unroll
        for (int f = 0; f < 16; f++)
#pragma unroll
            for (int v = 0; v < 4; v++) accS[f][v] = 0.f;
#pragma unroll
        for (int ks = 0; ks < 4; ks++) {
            uint32_t a[4];
            ldsm_x4(a, uQ + (aOffQ + ks * 16) * 2u);
#pragma unroll
            for (int fp = 0; fp < 8; fp++) {
                uint32_t r[4];
                ldsm_x4(r, uK + (bOffK + fp * 16 * 72 + ks * 16) * 2u);
                uint32_t b0[2] = {r[0], r[1]};
                uint32_t b1[2] = {r[2], r[3]};
                mma_f16(accS[2 * fp], a, b0);
                mma_f16(accS[2 * fp + 1], a, b1);
            }
        }

        {
            int kn = (it + 1 < t1) ? (it + 1) : (t1 - 1);
            load_k(kn, ((li + 1) & 1) ? uKb : uKa);
            CP_COMMIT();
        }

        CP_WAIT1();
        __syncthreads();

        const int k0 = it * 128;
        const bool lastT = (it == nT - 1);
        const int lim0 = MEMN + qg0 - k0;
        const int lim1 = lim0 + 8;

        __half* p0 = sP + lr0 * 136;
        __half* p1 = p0 + 8 * 136;

        float rm0 = -1e30f, rm1 = -1e30f;
#pragma unroll
        for (int fn = 0; fn < 16; fn++) {
            int kc = fn * 8 + 2 * c4;
            float2 f0 = __half22float2(*(const __half2*)(p0 + kc));
            float2 f1 = __half22float2(*(const __half2*)(p1 + kc));
            float s0, s1, s2, s3;
            s0 = (!lastT || kc     <= lim0) ? (accS[fn][0] + f0.x) * 0.125f : -1e30f;
            s1 = (!lastT || kc + 1 <= lim0) ? (accS[fn][1] + f0.y) * 0.125f : -1e30f;
            s2 = (!lastT || kc     <= lim1) ? (accS[fn][2] + f1.x) * 0.125f : -1e30f;
            s3 = (!lastT || kc + 1 <= lim1) ? (accS[fn][3] + f1.y) * 0.125f : -1e30f;
            accS[fn][0] = s0; accS[fn][1] = s1; accS[fn][2] = s2; accS[fn][3] = s3;
            rm0 = fmaxf(rm0, fmaxf(s0, s1));
            rm1 = fmaxf(rm1, fmaxf(s2, s3));
        }
        rm0 = fmaxf(rm0, __shfl_xor_sync(~0u, rm0, 1));
        rm0 = fmaxf(rm0, __shfl_xor_sync(~0u, rm0, 2));
        rm1 = fmaxf(rm1, __shfl_xor_sync(~0u, rm1, 1));
        rm1 = fmaxf(rm1, __shfl_xor_sync(~0u, rm1, 2));
        float mN0 = fmaxf(m0, rm0), mN1 = fmaxf(m1, rm1);
        float al0 = __expf(m0 - mN0), al1 = __expf(m1 - mN1);
        m0 = mN0; m1 = mN1;

        float ps0 = 0.f, ps1 = 0.f;
#pragma unroll
        for (int fn = 0; fn < 16; fn++) {
            int kc = fn * 8 + 2 * c4;
            float e0 = __expf(accS[fn][0] - m0);
            float e1 = __expf(accS[fn][1] - m0);
            float e2 = __expf(accS[fn][2] - m1);
            float e3 = __expf(accS[fn][3] - m1);
            ps0 += e0 + e1; ps1 += e2 + e3;
            *(__half2*)(p0 + kc) = __floats2half2_rn(e0, e1);
            *(__half2*)(p1 + kc) = __floats2half2_rn(e2, e3);
        }
        ps0 += __shfl_xor_sync(~0u, ps0, 1); ps0 += __shfl_xor_sync(~0u, ps0, 2);
        ps1 += __shfl_xor_sync(~0u, ps1, 1); ps1 += __shfl_xor_sync(~0u, ps1, 2);
        l0 = l0 * al0 + ps0;
        l1 = l1 * al1 + ps1;
#pragma unroll
        for (int f = 0; f < 8; f++) {
            accO[f][0] *= al0; accO[f][1] *= al0;
            accO[f][2] *= al1; accO[f][3] *= al1;
        }
        __syncwarp();

#pragma unroll
        for (int ks = 0; ks < 8; ks++) {
            uint32_t a[4];
            ldsm_x4(a, uP + (aOffP + ks * 16) * 2u);
#pragma unroll
            for (int fp = 0; fp < 4; fp++) {
                uint32_t r[4];
                ldsm_x4t(r, uV + (bOffV + ks * 16 * 72 + fp * 16) * 2u);
                uint32_t b0[2] = {r[0], r[1]};
                uint32_t b1[2] = {r[2], r[3]};
                mma_f16(accO[2 * fp], a, b0);
                mma_f16(accO[2 * fp + 1], a, b1);
            }
        }
        __syncthreads();

        {
            int vn = (it + 1 < t1) ? (it + 1) : (t1 - 1);
            load_sr(vn);
            load_v(vn);
            CP_COMMIT();
        }
    }

    const size_t base0 = ((size_t)b * HH + h) * QQ + qg0;
    const size_t base1 = base0 + 8;
    float* o0 = g_opart + (base0 * KSPLIT + split) * DHH;
    float* o1 = g_opart + (base1 * KSPLIT + split) * DHH;
#pragma unroll
    for (int fn = 0; fn < 8; fn++) {
        int col = fn * 8 + 2 * c4;
        *(float2*)(o0 + col) = make_float2(accO[fn][0], accO[fn][1]);
        *(float2*)(o1 + col) = make_float2(accO[fn][2], accO[fn][3]);
    }
    if (c4 == 0) {
        float* ml0 = g_ml + (base0 * KSPLIT + split) * 2;
        float* ml1 = g_ml + (base1 * KSPLIT + split) * 2;
        ml0[0] = m0; ml0[1] = l0;
        ml1[0] = m1; ml1[1] = l1;
    }
}

// ---------------------------------------------------------------------------
// Combine split-K partials -> ctx (fp16)
// ---------------------------------------------------------------------------
__global__ void __launch_bounds__(256) combine_kernel() {
    const int col = threadIdx.x & 63;
    const int rloc = threadIdx.x >> 6;
    const int q = blockIdx.x * 4 + rloc;
    const int h = blockIdx.y, b = blockIdx.z;
    const size_t base = ((size_t)b * HH + h) * QQ + q;

    float m[KSPLIT], l[KSPLIT];
#pragma unroll
    for (int s = 0; s < KSPLIT; s++) {
        m[s] = g_ml[(base * KSPLIT + s) * 2 + 0];
        l[s] = g_ml[(base * KSPLIT + s) * 2 + 1];
    }
    float mx = m[0];
#pragma unroll
    for (int s = 1; s < KSPLIT; s++) mx = fmaxf(mx, m[s]);
    float w[KSPLIT], L = 0.f;
#pragma unroll
    for (int s = 0; s < KSPLIT; s++) { w[s] = __expf(m[s] - mx); L += l[s] * w[s]; }
    const float inv = 1.0f / L;

    float o = 0.f;
#pragma unroll
    for (int s = 0; s < KSPLIT; s++)
        o += g_opart[(base * KSPLIT + s) * DHH + col] * w[s];
    g_ctxh[((size_t)b * QQ + q) * UU + h * 64 + col] = __float2half(o * inv);
}

// ---------------------------------------------------------------------------
// Launch
// ---------------------------------------------------------------------------
extern "C" void kernel_launch(void* const* d_in, const int* in_sizes, int n_in,
                              void* d_out, int out_size) {
    const float* inputs    = (const float*)d_in[0];
    const float* relatives = (const float*)d_in[1];
    const float* memories  = (const float*)d_in[2];
    const float* bias_c    = (const float*)d_in[3];
    const float* bias_r    = (const float*)d_in[4];
    const float* Wq        = (const float*)d_in[5];
    const float* Wkv       = (const float*)d_in[6];
    const float* Wr        = (const float*)d_in[7];
    const float* Wo        = (const float*)d_in[8];
    float* out             = (float*)d_out;

    constexpr int SMEM_G  = 4 * (128 + 128) * G_LDSS * 2;                // 81920
    constexpr int SMEM_SR = 2 * (128 + 128) * G_LDSS * 2;                // 40960
    constexpr int SMEM_F  = (3 * 128 * 72 + 128 * 72 + 128 * 136) * 2;   // 108544
    cudaFuncSetAttribute((const void*)proj_kernel,
                         cudaFuncAttributeMaxDynamicSharedMemorySize, SMEM_G);
    cudaFuncSetAttribute((const void*)wo_kernel,
                         cudaFuncAttributeMaxDynamicSharedMemorySize, SMEM_G);
    cudaFuncSetAttribute((const void*)sr_kernel,
                         cudaFuncAttributeMaxDynamicSharedMemorySize, SMEM_SR);
    cudaFuncSetAttribute((const void*)flash_kernel,
                         cudaFuncAttributeMaxDynamicSharedMemorySize, SMEM_F);

    // 0. all weight transposes in one launch
    wtrans_kernel<<<5120, dim3(32, 8)>>>(Wq, Wkv, Wr, Wo);

    // 1. fullh = fp16(concat); relrh = fp16(relatives)
    {
        size_t total4 = (size_t)BB * KL * UU / 4;
        prep_kernel<<<(unsigned)((2 * total4 + 255) / 256), 256>>>(memories, inputs, relatives);
    }

    // 2. merged projections: wkv | wr | wq  (896 CTAs, one launch)
    proj_kernel<<<896, 256, SMEM_G>>>(bias_c, bias_r);

    // 3. SrShift = shifted (qr @ wr^T), SMEM-staged coalesced store
    sr_kernel<<<dim3(KL / 128, QQ / 128, BB * HH), 256, SMEM_SR>>>();

    // 4. split-K fused fp16 flash -> partials
    flash_kernel<<<dim3(8 * KSPLIT, HH, BB), 256, SMEM_F>>>();

    // 5. combine partials -> ctx (fp16)
    combine_kernel<<<dim3(QQ / 4, HH, BB), 256>>>();

    // 6. out = ctx @ Wo (fp32 out)
    wo_kernel<<<dim3(UU / 128, (BB * QQ) / 128, 1), 256, SMEM_G>>>(out);
}

// round 15
// speedup vs baseline: 1.4817x; 1.0050x over previous
#include <cuda_runtime.h>
#include <cuda_fp16.h>
#include <cstdint>

// Problem constants
#define BB   2
#define QQ   1024
#define MEMN 1024
#define UU   1024
#define HH   16
#define DHH  64
#define KL   2048   // MEM + Q
#define KSPLIT 3

// ---------------------------------------------------------------------------
// Scratch (allocation-free: __device__ globals, 16B-aligned for cp.async)
// ---------------------------------------------------------------------------
__device__ __align__(16) __half g_fullh[(size_t)BB * KL * UU];     // fp16 concat
__device__ __align__(16) __half g_relrh[(size_t)BB * KL * UU];     // fp16 relatives
__device__ __align__(16) __half g_qch [(size_t)BB * QQ * UU];      // fp16 q + bias_c
__device__ __align__(16) __half g_qrh [(size_t)BB * QQ * UU];      // fp16 q + bias_r
__device__ __align__(16) __half g_kh  [(size_t)BB * KL * UU];      // fp16 K
__device__ __align__(16) __half g_vh  [(size_t)BB * KL * UU];      // fp16 V  [b,t,u]
__device__ __align__(16) __half g_wrh [(size_t)BB * KL * UU];      // fp16 w_r
__device__ __align__(16) __half g_srh [(size_t)BB * HH * QQ * KL]; // fp16 Sr SHIFTED
__device__ __align__(16) __half g_ctxh[(size_t)BB * QQ * UU];      // fp16 attention out
__device__ __align__(16) __half g_wqTh [(size_t)UU * UU];
__device__ __align__(16) __half g_wkvTh[(size_t)2 * UU * UU];
__device__ __align__(16) __half g_wrTh [(size_t)UU * UU];
__device__ __align__(16) __half g_woTh [(size_t)UU * UU];
__device__ float g_opart[(size_t)BB * HH * QQ * KSPLIT * DHH];
__device__ float g_ml   [(size_t)BB * HH * QQ * KSPLIT * 2];

// ---------------------------------------------------------------------------
// Helpers
// ---------------------------------------------------------------------------
__device__ __forceinline__ uint32_t smem_to_u32(const void* p) {
    uint32_t a;
    asm("{ .reg .u64 t; cvta.to.shared.u64 t, %1; cvt.u32.u64 %0, t; }" : "=r"(a) : "l"(p));
    return a;
}
__device__ __forceinline__ void cp_async16(uint32_t saddr, const void* gaddr) {
    asm volatile("cp.async.cg.shared.global [%0], [%1], 16;" :: "r"(saddr), "l"(gaddr));
}
#define CP_COMMIT() asm volatile("cp.async.commit_group;" ::: "memory")
#define CP_WAIT0()  asm volatile("cp.async.wait_group 0;" ::: "memory")
#define CP_WAIT1()  asm volatile("cp.async.wait_group 1;" ::: "memory")
#define CP_WAIT2()  asm volatile("cp.async.wait_group 2;" ::: "memory")

__device__ __forceinline__ void mma_f16(float acc[4], const uint32_t a[4], const uint32_t b[2]) {
    asm volatile("mma.sync.aligned.m16n8k16.row.col.f32.f16.f16.f32 "
        "{%0,%1,%2,%3}, {%4,%5,%6,%7}, {%8,%9}, {%0,%1,%2,%3};"
        : "+f"(acc[0]), "+f"(acc[1]), "+f"(acc[2]), "+f"(acc[3])
        : "r"(a[0]), "r"(a[1]), "r"(a[2]), "r"(a[3]), "r"(b[0]), "r"(b[1]));
}
__device__ __forceinline__ void ldsm_x4(uint32_t* r, uint32_t addr) {
    asm volatile("ldmatrix.sync.aligned.m8n8.x4.shared.b16 {%0,%1,%2,%3}, [%4];"
        : "=r"(r[0]), "=r"(r[1]), "=r"(r[2]), "=r"(r[3]) : "r"(addr));
}
__device__ __forceinline__ void ldsm_x4t(uint32_t* r, uint32_t addr) {
    asm volatile("ldmatrix.sync.aligned.m8n8.x4.trans.shared.b16 {%0,%1,%2,%3}, [%4];"
        : "=r"(r[0]), "=r"(r[1]), "=r"(r[2]), "=r"(r[3]) : "r"(addr));
}

// ---------------------------------------------------------------------------
// Fused setup: weight transposes + fp16 conversions of concat/relatives,
// one launch. Blocks [0,5120) = transposes; [5120, 21504) = prep copies.
// ---------------------------------------------------------------------------
__global__ void __launch_bounds__(256)
setup_kernel(const float* __restrict__ mem, const float* __restrict__ inp,
             const float* __restrict__ rel,
             const float* __restrict__ Wq, const float* __restrict__ Wkv,
             const float* __restrict__ Wr, const float* __restrict__ Wo) {
    const int tid = threadIdx.x;
    int bid = blockIdx.x;
    if (bid < 5120) {
        // ---- weight transpose: W[K=1024, N] fp32 -> W^T[N, 1024] fp16 ----
        __shared__ float t[32][33];
        const float* in; __half* out; int cols;
        if (bid < 1024)      { in = Wq;  out = g_wqTh;  cols = 1024; }
        else if (bid < 3072) { in = Wkv; out = g_wkvTh; cols = 2048; bid -= 1024; }
        else if (bid < 4096) { in = Wr;  out = g_wrTh;  cols = 1024; bid -= 3072; }
        else                 { in = Wo;  out = g_woTh;  cols = 1024; bid -= 4096; }
        int tilesX = cols / 32;
        int c0 = (bid % tilesX) * 32;
        int r0 = (bid / tilesX) * 32;
        int tx = tid & 31, ty = tid >> 5;
#pragma unroll
        for (int i = 0; i < 32; i += 8)
            t[ty + i][tx] = in[(size_t)(r0 + ty + i) * cols + c0 + tx];
        __syncthreads();
#pragma unroll
        for (int i = 0; i < 32; i += 8)
            out[(size_t)(c0 + ty + i) * 1024 + r0 + tx] = __float2half(t[tx][ty + i]);
    } else {
        // ---- prep: concat(mem, inp) -> g_fullh ; rel -> g_relrh ----
        const size_t total4 = (size_t)BB * KL * UU / 4;
        size_t i = (size_t)(bid - 5120) * 256 + tid;
        if (i < total4) {
            size_t elem = i * 4;
            int b = (int)(elem / ((size_t)KL * UU));
            size_t rem = elem % ((size_t)KL * UU);
            int t = (int)(rem / UU);
            int u = (int)(rem % UU);
            float4 v;
            if (t < MEMN) v = *(const float4*)(mem + ((size_t)b * MEMN + t) * UU + u);
            else          v = *(const float4*)(inp + ((size_t)b * QQ + (t - MEMN)) * UU + u);
            __half2* o = (__half2*)(g_fullh + elem);
            o[0] = __floats2half2_rn(v.x, v.y);
            o[1] = __floats2half2_rn(v.z, v.w);
        } else if (i < 2 * total4) {
            size_t j = i - total4;
            float4 v = ((const float4*)rel)[j];
            __half2* o = (__half2*)(g_relrh + j * 4);
            o[0] = __floats2half2_rn(v.x, v.y);
            o[1] = __floats2half2_rn(v.z, v.w);
        }
    }
}

// ===========================================================================
// Shared GEMM constants (KC=32)
// ===========================================================================
#define G_LDSS 40
#define G_KC   32

// ---------------------------------------------------------------------------
// Merged projection GEMM: one launch covers wkv (EPI4), wr (EPI3), wq (EPI2).
// Flat grid: [0,512) wkv | [512,768) wr | [768,896) wq. 4-stage pipeline.
// ---------------------------------------------------------------------------
__global__ void __launch_bounds__(256)
proj_kernel(const float* __restrict__ bc, const float* __restrict__ br) {
    constexpr int BM = 128, BN = 128, WM = 64, WN = 32;
    constexpr int MFRAG = WM / 16, NFRAG = WN / 8;

    int cta = blockIdx.x;
    int epi;
    const __half* A;
    const __half* Bw;
    __half *Ch = nullptr, *C2h = nullptr;
    int bm, bn;
    if (cta < 512) {               // wkv
        epi = 4;
        int bx = cta & 15, by = cta >> 4;
        A = g_fullh; Bw = g_wkvTh;
        Ch = g_vh; C2h = g_kh;
        bm = by * BM; bn = bx * BN;
    } else if (cta < 768) {        // wr
        epi = 3;
        int c = cta - 512;
        int bx = c & 7, by = c >> 3;
        A = g_relrh; Bw = g_wrTh;
        Ch = g_wrh;
        bm = by * BM; bn = bx * BN;
    } else {                       // wq
        epi = 2;
        int c = cta - 768;
        int bx = c & 7, by = (c >> 3) & 7, zz = c >> 6;
        A = g_fullh + (size_t)MEMN * UU + (size_t)zz * KL * UU;
        Bw = g_wqTh;
        Ch = g_qch + (size_t)zz * QQ * UU;
        C2h = g_qrh + (size_t)zz * QQ * UU;
        bm = by * BM; bn = bx * BN;
    }
    const int lda = UU, ldb = UU, ldc = UU;
    const int nIter = UU / G_KC;   // 32

    extern __shared__ __half smh[];
    __half* As = smh;
    __half* Bs = smh + 4 * BM * G_LDSS;
    const uint32_t sA_base = smem_to_u32(As);
    const uint32_t sB_base = smem_to_u32(Bs);

    const int tid = threadIdx.x;
    const int lane = tid & 31;
    const int warp = tid >> 5;
    const int wm = warp & 1;
    const int wn = warp >> 1;
    const __half* Ag = A + (size_t)bm * lda;
    const __half* Bg = Bw + (size_t)bn * ldb;

    auto load_stage = [&](int stage, int buf) {
#pragma unroll
        for (int i = 0; i < 2; i++) {
            int idx = tid + i * 256;
            int row = idx >> 2, ch = idx & 3;
            uint32_t s = sA_base + (uint32_t)(buf * BM * G_LDSS + row * G_LDSS + ch * 8) * 2u;
            cp_async16(s, Ag + (size_t)row * lda + stage * G_KC + ch * 8);
        }
#pragma unroll
        for (int i = 0; i < 2; i++) {
            int idx = tid + i * 256;
            int row = idx >> 2, ch = idx & 3;
            uint32_t s = sB_base + (uint32_t)(buf * BN * G_LDSS + row * G_LDSS + ch * 8) * 2u;
            cp_async16(s, Bg + (size_t)row * ldb + stage * G_KC + ch * 8);
        }
    };

    float acc[MFRAG][NFRAG][4];
#pragma unroll
    for (int i = 0; i < MFRAG; i++)
#pragma unroll
        for (int j = 0; j < NFRAG; j++)
#pragma unroll
            for (int v = 0; v < 4; v++) acc[i][j][v] = 0.0f;

    load_stage(0, 0); CP_COMMIT();
    load_stage(1, 1); CP_COMMIT();
    load_stage(2, 2); CP_COMMIT();

    const uint32_t aOff = (uint32_t)((wm * WM + (lane & 15)) * G_LDSS + (lane >> 4) * 8);
    const uint32_t bOff = (uint32_t)((wn * WN + (lane & 7) + (lane >> 4) * 8) * G_LDSS +
                                     ((lane >> 3) & 1) * 8);
    const int r4 = lane >> 2;
    const int c4 = lane & 3;

    for (int it = 0; it < nIter; ++it) {
        CP_WAIT2();
        __syncthreads();
        if (it + 3 < nIter) load_stage(it + 3, (it + 3) & 3);
        CP_COMMIT();

        const uint32_t aBuf = sA_base + (uint32_t)((it & 3) * BM * G_LDSS) * 2u;
        const uint32_t bBuf = sB_base + (uint32_t)((it & 3) * BN * G_LDSS) * 2u;

#pragma unroll
        for (int ks = 0; ks < 2; ks++) {
            uint32_t af[MFRAG][4];
            uint32_t bf[NFRAG][2];
#pragma unroll
            for (int fm = 0; fm < MFRAG; fm++)
                ldsm_x4(af[fm], aBuf + (aOff + fm * 16 * G_LDSS + ks * 16) * 2u);
#pragma unroll
            for (int fp = 0; fp < NFRAG / 2; fp++) {
                uint32_t r[4];
                ldsm_x4(r, bBuf + (bOff + fp * 16 * G_LDSS + ks * 16) * 2u);
                bf[2 * fp][0] = r[0]; bf[2 * fp][1] = r[1];
                bf[2 * fp + 1][0] = r[2]; bf[2 * fp + 1][1] = r[3];
            }
#pragma unroll
            for (int fm = 0; fm < MFRAG; fm++)
#pragma unroll
                for (int fn = 0; fn < NFRAG; fn++)
                    mma_f16(acc[fm][fn], af[fm], bf[fn]);
        }
    }

    const int m0 = bm + wm * WM;
    const int n0 = bn + wn * WN;
#pragma unroll
    for (int fm = 0; fm < MFRAG; fm++) {
#pragma unroll
        for (int fn = 0; fn < NFRAG; fn++) {
            int r = m0 + fm * 16 + r4;
            int cidx = n0 + fn * 8 + c4 * 2;
            float a0 = acc[fm][fn][0], a1 = acc[fm][fn][1];
            float a2 = acc[fm][fn][2], a3 = acc[fm][fn][3];
            if (epi == 4) {
                if (cidx < UU) {
                    *(__half2*)(C2h + (size_t)r * UU + cidx) = __floats2half2_rn(a0, a1);
                    *(__half2*)(C2h + (size_t)(r + 8) * UU + cidx) = __floats2half2_rn(a2, a3);
                } else {
                    *(__half2*)(Ch + (size_t)r * UU + cidx - UU) = __floats2half2_rn(a0, a1);
                    *(__half2*)(Ch + (size_t)(r + 8) * UU + cidx - UU) = __floats2half2_rn(a2, a3);
                }
            } else if (epi == 3) {
                *(__half2*)(Ch + (size_t)r * ldc + cidx) = __floats2half2_rn(a0, a1);
                *(__half2*)(Ch + (size_t)(r + 8) * ldc + cidx) = __floats2half2_rn(a2, a3);
            } else {  // epi == 2
                float b0 = bc[cidx], b1 = bc[cidx + 1];
                float r0 = br[cidx], r1 = br[cidx + 1];
                *(__half2*)(Ch + (size_t)r * ldc + cidx) = __floats2half2_rn(a0 + b0, a1 + b1);
                *(__half2*)(Ch + (size_t)(r + 8) * ldc + cidx) = __floats2half2_rn(a2 + b0, a3 + b1);
                *(__half2*)(C2h + (size_t)r * ldc + cidx) = __floats2half2_rn(a0 + r0, a1 + r1);
                *(__half2*)(C2h + (size_t)(r + 8) * ldc + cidx) = __floats2half2_rn(a2 + r0, a3 + r1);
            }
        }
    }
}

// ---------------------------------------------------------------------------
// Sr shifted GEMM, K=64 specialized (exact R12 config): 2 flat K-chunks,
// SMEM-staged coalesced shifted store. Grid (KL/128, QQ/128, BB*HH).
// ---------------------------------------------------------------------------
__global__ void __launch_bounds__(256)
sr_kernel() {
    constexpr int BM = 128, BN = 128, WM = 64, WN = 32;
    constexpr int MFRAG = WM / 16, NFRAG = WN / 8;

    const int bm = blockIdx.y * BM;
    const int bn = blockIdx.x * BN;
    if (bn + bm + BM + BN - 2 - (QQ - 1) < 0) return;  // fully below shift diagonal

    const int z = blockIdx.z;          // b*HH + h
    const int z1 = z / HH, z2 = z % HH;
    const __half* A = g_qrh + (size_t)z1 * QQ * UU + (size_t)z2 * 64;
    const __half* B = g_wrh + (size_t)z1 * KL * UU + (size_t)z2 * 64;
    __half* C = g_srh + (size_t)z * QQ * KL;

    extern __shared__ __half smh[];
    __half* As = smh;                       // [2][128][40]
    __half* Bs = smh + 2 * BM * G_LDSS;     // [2][128][40]
    const uint32_t sA_base = smem_to_u32(As);
    const uint32_t sB_base = smem_to_u32(Bs);

    const int tid = threadIdx.x;
    const int lane = tid & 31;
    const int warp = tid >> 5;
    const int wm = warp & 1;
    const int wn = warp >> 1;
    const __half* Ag = A + (size_t)bm * UU;
    const __half* Bg = B + (size_t)bn * UU;

    // load both K chunks
#pragma unroll
    for (int st = 0; st < 2; st++) {
#pragma unroll
        for (int i = 0; i < 2; i++) {
            int idx = tid + i * 256;
            int row = idx >> 2, ch = idx & 3;
            cp_async16(sA_base + (uint32_t)(st * BM * G_LDSS + row * G_LDSS + ch * 8) * 2u,
                       Ag + (size_t)row * UU + st * G_KC + ch * 8);
        }
#pragma unroll
        for (int i = 0; i < 2; i++) {
            int idx = tid + i * 256;
            int row = idx >> 2, ch = idx & 3;
            cp_async16(sB_base + (uint32_t)(st * BN * G_LDSS + row * G_LDSS + ch * 8) * 2u,
                       Bg + (size_t)row * UU + st * G_KC + ch * 8);
        }
        CP_COMMIT();
    }
    CP_WAIT0();
    __syncthreads();

    const uint32_t aOff = (uint32_t)((wm * WM + (lane & 15)) * G_LDSS + (lane >> 4) * 8);
    const uint32_t bOff = (uint32_t)((wn * WN + (lane & 7) + (lane >> 4) * 8) * G_LDSS +
                                     ((lane >> 3) & 1) * 8);
    const int r4 = lane >> 2;
    const int c4 = lane & 3;

    float acc[MFRAG][NFRAG][4];
#pragma unroll
    for (int i = 0; i < MFRAG; i++)
#pragma unroll
        for (int j = 0; j < NFRAG; j++)
#pragma unroll
            for (int v = 0; v < 4; v++) acc[i][j][v] = 0.0f;

#pragma unroll
    for (int st = 0; st < 2; st++) {
        const uint32_t aBuf = sA_base + (uint32_t)(st * BM * G_LDSS) * 2u;
        const uint32_t bBuf = sB_base + (uint32_t)(st * BN * G_LDSS) * 2u;
#pragma unroll
        for (int ks = 0; ks < 2; ks++) {
            uint32_t af[MFRAG][4];
            uint32_t bf[NFRAG][2];
#pragma unroll
            for (int fm = 0; fm < MFRAG; fm++)
                ldsm_x4(af[fm], aBuf + (aOff + fm * 16 * G_LDSS + ks * 16) * 2u);
#pragma unroll
            for (int fp = 0; fp < NFRAG / 2; fp++) {
                uint32_t r[4];
                ldsm_x4(r, bBuf + (bOff + fp * 16 * G_LDSS + ks * 16) * 2u);
                bf[2 * fp][0] = r[0]; bf[2 * fp][1] = r[1];
                bf[2 * fp + 1][0] = r[2]; bf[2 * fp + 1][1] = r[3];
            }
#pragma unroll
            for (int fm = 0; fm < MFRAG; fm++)
#pragma unroll
                for (int fn = 0; fn < NFRAG; fn++)
                    mma_f16(acc[fm][fn], af[fm], bf[fn]);
        }
    }

    // ---- stage C tile in SMEM [128][136] (reuse A/B buffers) ----
    __syncthreads();
    __half* Cs = smh;
    const int m0l = wm * WM;
    const int n0l = wn * WN;
#pragma unroll
    for (int fm = 0; fm < MFRAG; fm++) {
#pragma unroll
        for (int fn = 0; fn < NFRAG; fn++) {
            int lr = m0l + fm * 16 + r4;
            int lc = n0l + fn * 8 + 2 * c4;
            *(__half2*)(Cs + lr * 136 + lc) =
                __floats2half2_rn(acc[fm][fn][0], acc[fm][fn][1]);
            *(__half2*)(Cs + (lr + 8) * 136 + lc) =
                __floats2half2_rn(acc[fm][fn][2], acc[fm][fn][3]);
        }
    }
    __syncthreads();

    // ---- coalesced shifted store: 2 rows per pass, 128 threads per row ----
    const int col = tid & 127;
    const int off = bn - (QQ - 1) + bm;   // k of (row 0, col 0)
#pragma unroll 4
    for (int r = tid >> 7; r < 128; r += 2) {
        int k = off + r + col;            // k = bn + col - (Q-1) + (bm + r)
        if (k >= 0)
            C[(size_t)(bm + r) * KL + k] = Cs[r * 136 + col];
    }
}

// ---------------------------------------------------------------------------
// Wo GEMM: BN=64 (WN=16) -> 256 CTAs, 2/SM for latency overlap.
// Grid (16, 16, 1), fp32 out.
// ---------------------------------------------------------------------------
__global__ void __launch_bounds__(256)
wo_kernel(float* __restrict__ out) {
    constexpr int BM = 128, BN = 64, WM = 64, WN = 16;
    constexpr int MFRAG = WM / 16, NFRAG = WN / 8;

    const int bm = blockIdx.y * BM;
    const int bn = blockIdx.x * BN;

    extern __shared__ __half smh[];
    __half* As = smh;
    __half* Bs = smh + 4 * BM * G_LDSS;
    const uint32_t sA_base = smem_to_u32(As);
    const uint32_t sB_base = smem_to_u32(Bs);

    const int tid = threadIdx.x;
    const int lane = tid & 31;
    const int warp = tid >> 5;
    const int wm = warp & 1;
    const int wn = warp >> 1;
    const __half* Ag = g_ctxh + (size_t)bm * UU;
    const __half* Bg = g_woTh + (size_t)bn * UU;
    const int nIter = UU / G_KC;

    auto load_stage = [&](int stage, int buf) {
#pragma unroll
        for (int i = 0; i < 2; i++) {
            int idx = tid + i * 256;
            int row = idx >> 2, ch = idx & 3;
            cp_async16(sA_base + (uint32_t)(buf * BM * G_LDSS + row * G_LDSS + ch * 8) * 2u,
                       Ag + (size_t)row * UU + stage * G_KC + ch * 8);
        }
        {
            int idx = tid;
            int row = idx >> 2, ch = idx & 3;
            cp_async16(sB_base + (uint32_t)(buf * BN * G_LDSS + row * G_LDSS + ch * 8) * 2u,
                       Bg + (size_t)row * UU + stage * G_KC + ch * 8);
        }
    };

    float acc[MFRAG][NFRAG][4];
#pragma unroll
    for (int i = 0; i < MFRAG; i++)
#pragma unroll
        for (int j = 0; j < NFRAG; j++)
#pragma unroll
            for (int v = 0; v < 4; v++) acc[i][j][v] = 0.0f;

    load_stage(0, 0); CP_COMMIT();
    load_stage(1, 1); CP_COMMIT();
    load_stage(2, 2); CP_COMMIT();

    const uint32_t aOff = (uint32_t)((wm * WM + (lane & 15)) * G_LDSS + (lane >> 4) * 8);
    const uint32_t bOff = (uint32_t)((wn * WN + (lane & 7) + (lane >> 4) * 8) * G_LDSS +
                                     ((lane >> 3) & 1) * 8);
    const int r4 = lane >> 2;
    const int c4 = lane & 3;

    for (int it = 0; it < nIter; ++it) {
        CP_WAIT2();
        __syncthreads();
        if (it + 3 < nIter) load_stage(it + 3, (it + 3) & 3);
        CP_COMMIT();

        const uint32_t aBuf = sA_base + (uint32_t)((it & 3) * BM * G_LDSS) * 2u;
        const uint32_t bBuf = sB_base + (uint32_t)((it & 3) * BN * G_LDSS) * 2u;

#pragma unroll
        for (int ks = 0; ks < 2; ks++) {
            uint32_t af[MFRAG][4];
            uint32_t bf[NFRAG][2];
#pragma unroll
            for (int fm = 0; fm < MFRAG; fm++)
                ldsm_x4(af[fm], aBuf + (aOff + fm * 16 * G_LDSS + ks * 16) * 2u);
            {
                uint32_t r[4];
                ldsm_x4(r, bBuf + (bOff + ks * 16) * 2u);
                bf[0][0] = r[0]; bf[0][1] = r[1];
                bf[1][0] = r[2]; bf[1][1] = r[3];
            }
#pragma unroll
            for (int fm = 0; fm < MFRAG; fm++)
#pragma unroll
                for (int fn = 0; fn < NFRAG; fn++)
                    mma_f16(acc[fm][fn], af[fm], bf[fn]);
        }
    }

    const int m0 = bm + wm * WM;
    const int n0 = bn + wn * WN;
#pragma unroll
    for (int fm = 0; fm < MFRAG; fm++) {
#pragma unroll
        for (int fn = 0; fn < NFRAG; fn++) {
            int r = m0 + fm * 16 + r4;
            int cidx = n0 + fn * 8 + c4 * 2;
            *(float2*)(out + (size_t)r * UU + cidx) =
                make_float2(acc[fm][fn][0], acc[fm][fn][1]);
            *(float2*)(out + (size_t)(r + 8) * UU + cidx) =
                make_float2(acc[fm][fn][2], acc[fm][fn][3]);
        }
    }
}

// ---------------------------------------------------------------------------
// Split-K fused fp16 flash attention (R12 version: P through SMEM).
// Grid (8*KSPLIT, H, B), 256 threads, 2 CTAs/SM.
// ---------------------------------------------------------------------------
__global__ void __launch_bounds__(256, 2) flash_kernel() {
    extern __shared__ __half smh[];
    __half* sQ  = smh;                  // [128][72]
    __half* sKa = sQ  + 128 * 72;
    __half* sKb = sKa + 128 * 72;
    __half* sV  = sKb + 128 * 72;       // [128 t][72 d]
    __half* sP  = sV  + 128 * 72;       // [128][136]
    const uint32_t uQ  = smem_to_u32(sQ);
    const uint32_t uKa = smem_to_u32(sKa);
    const uint32_t uKb = smem_to_u32(sKb);
    const uint32_t uV  = smem_to_u32(sV);
    const uint32_t uP  = smem_to_u32(sP);

    const int tid = threadIdx.x, lane = tid & 31, warp = tid >> 5;
    const int r4 = lane >> 2, c4 = lane & 3;
    const int qs = (int)blockIdx.x;
    const int qt = 7 - (qs / KSPLIT);
    const int split = qs % KSPLIT;
    const int h = blockIdx.y, b = blockIdx.z;
    const int q0 = qt * 128;
    const int nT = 9 + qt;
    const int t0 = (split * nT) / KSPLIT;
    const int t1 = ((split + 1) * nT) / KSPLIT;

    const __half* gQ = g_qch + ((size_t)b * QQ + q0) * UU + h * 64;
    const __half* gK = g_kh  + (size_t)b * KL * UU + h * 64;
    const __half* gV = g_vh  + (size_t)b * KL * UU + h * 64;
    const __half* gS = g_srh + (((size_t)b * HH + h) * QQ + q0) * KL;

    auto load_k = [&](int t, uint32_t dK) {
        const __half* src = gK + (size_t)t * 128 * UU;
        int i = tid;
#pragma unroll
        for (int rep = 0; rep < 4; rep++, i += 256) {
            int r = i >> 3, c = i & 7;
            cp_async16(dK + (uint32_t)(r * 72 + c * 8) * 2u, src + (size_t)r * UU + c * 8);
        }
    };
    auto load_v = [&](int t) {
        const __half* src = gV + (size_t)t * 128 * UU;
        int i = tid;
#pragma unroll
        for (int rep = 0; rep < 4; rep++, i += 256) {
            int r = i >> 3, c = i & 7;
            cp_async16(uV + (uint32_t)(r * 72 + c * 8) * 2u, src + (size_t)r * UU + c * 8);
        }
    };
    auto load_sr = [&](int t) {
        const __half* src = gS + (size_t)t * 128;
        int i = tid;
#pragma unroll
        for (int rep = 0; rep < 8; rep++, i += 256) {
            int r = i >> 4, c = i & 15;
            cp_async16(uP + (uint32_t)(r * 136 + c * 8) * 2u, src + (size_t)r * KL + c * 8);
        }
    };

    {
        int i = tid;
#pragma unroll
        for (int rep = 0; rep < 4; rep++, i += 256) {
            int r = i >> 3, c = i & 7;
            cp_async16(uQ + (uint32_t)(r * 72 + c * 8) * 2u, gQ + (size_t)r * UU + c * 8);
        }
        load_k(t0, uKa);
        CP_COMMIT();
        load_sr(t0);
        load_v(t0);
        CP_COMMIT();
    }

    const int lr0 = warp * 16 + r4;
    const int qg0 = q0 + lr0, qg1 = qg0 + 8;

    const uint32_t aOffQ = (uint32_t)((warp * 16 + (lane & 15)) * 72 + (lane >> 4) * 8);
    const uint32_t aOffP = (uint32_t)((warp * 16 + (lane & 15)) * 136 + (lane >> 4) * 8);
    const uint32_t bOffK = (uint32_t)(((lane & 7) + (lane >> 4) * 8) * 72 + ((lane >> 3) & 1) * 8);
    const uint32_t bOffV = (uint32_t)((lane & 15) * 72 + (lane >> 4) * 8);

    float m0 = -1e30f, m1 = -1e30f, l0 = 0.f, l1 = 0.f;
    float accO[8][4];
#pragma unroll
    for (int f = 0; f < 8; f++)
#pragma unroll
        for (int v = 0; v < 4; v++) accO[f][v] = 0.f;

    for (int it = t0; it < t1; ++it) {
        const int li = it - t0;
        const uint32_t uK = (li & 1) ? uKb : uKa;
        CP_WAIT1();
        __syncthreads();

        float accS[16][4];
#pragma unroll
        for (int f = 0; f < 16; f++)
#pragma unroll
            for (int v = 0; v < 4; v++) accS[f][v] = 0.f;
#pragma unroll
        for (int ks = 0; ks < 4; ks++) {
            uint32_t a[4];
            ldsm_x4(a, uQ + (aOffQ + ks * 16) * 2u);
#pragma unroll
            for (int fp = 0; fp < 8; fp++) {
                uint32_t r[4];
                ldsm_x4(r, uK + (bOffK + fp * 16 * 72 + ks * 16) * 2u);
                uint32_t b0[2] = {r[0], r[1]};
                uint32_t b1[2] = {r[2], r[3]};
                mma_f16(accS[2 * fp], a, b0);
                mma_f16(accS[2 * fp + 1], a, b1);
            }
        }

        {
            int kn = (it + 1 < t1) ? (it + 1) : (t1 - 1);
            load_k(kn, ((li + 1) & 1) ? uKb : uKa);
            CP_COMMIT();
        }

        CP_WAIT1();
        __syncthreads();

        const int k0 = it * 128;
        const bool lastT = (it == nT - 1);
        const int lim0 = MEMN + qg0 - k0;
        const int lim1 = lim0 + 8;

        __half* p0 = sP + lr0 * 136;
        __half* p1 = p0 + 8 * 136;

        float rm0 = -1e30f, rm1 = -1e30f;
#pragma unroll
        for (int fn = 0; fn < 16; fn++) {
            int kc = fn * 8 + 2 * c4;
            float2 f0 = __half22float2(*(const __half2*)(p0 + kc));
            float2 f1 = __half22float2(*(const __half2*)(p1 + kc));
            float s0, s1, s2, s3;
            s0 = (!lastT || kc     <= lim0) ? (accS[fn][0] + f0.x) * 0.125f : -1e30f;
            s1 = (!lastT || kc + 1 <= lim0) ? (accS[fn][1] + f0.y) * 0.125f : -1e30f;
            s2 = (!lastT || kc     <= lim1) ? (accS[fn][2] + f1.x) * 0.125f : -1e30f;
            s3 = (!lastT || kc + 1 <= lim1) ? (accS[fn][3] + f1.y) * 0.125f : -1e30f;
            accS[fn][0] = s0; accS[fn][1] = s1; accS[fn][2] = s2; accS[fn][3] = s3;
            rm0 = fmaxf(rm0, fmaxf(s0, s1));
            rm1 = fmaxf(rm1, fmaxf(s2, s3));
        }
        rm0 = fmaxf(rm0, __shfl_xor_sync(~0u, rm0, 1));
        rm0 = fmaxf(rm0, __shfl_xor_sync(~0u, rm0, 2));
        rm1 = fmaxf(rm1, __shfl_xor_sync(~0u, rm1, 1));
        rm1 = fmaxf(rm1, __shfl_xor_sync(~0u, rm1, 2));
        float mN0 = fmaxf(m0, rm0), mN1 = fmaxf(m1, rm1);
        float al0 = __expf(m0 - mN0), al1 = __expf(m1 - mN1);
        m0 = mN0; m1 = mN1;

        float ps0 = 0.f, ps1 = 0.f;
#pragma unroll
        for (int fn = 0; fn < 16; fn++) {
            int kc = fn * 8 + 2 * c4;
            float e0 = __expf(accS[fn][0] - m0);
            float e1 = __expf(accS[fn][1] - m0);
            float e2 = __expf(accS[fn][2] - m1);
            float e3 = __expf(accS[fn][3] - m1);
            ps0 += e0 + e1; ps1 += e2 + e3;
            *(__half2*)(p0 + kc) = __floats2half2_rn(e0, e1);
            *(__half2*)(p1 + kc) = __floats2half2_rn(e2, e3);
        }
        ps0 += __shfl_xor_sync(~0u, ps0, 1); ps0 += __shfl_xor_sync(~0u, ps0, 2);
        ps1 += __shfl_xor_sync(~0u, ps1, 1); ps1 += __shfl_xor_sync(~0u, ps1, 2);
        l0 = l0 * al0 + ps0;
        l1 = l1 * al1 + ps1;
#pragma unroll
        for (int f = 0; f < 8; f++) {
            accO[f][0] *= al0; accO[f][1] *= al0;
            accO[f][2] *= al1; accO[f][3] *= al1;
        }
        __syncwarp();

#pragma unroll
        for (int ks = 0; ks < 8; ks++) {
            uint32_t a[4];
            ldsm_x4(a, uP + (aOffP + ks * 16) * 2u);
#pragma unroll
            for (int fp = 0; fp < 4; fp++) {
                uint32_t r[4];
                ldsm_x4t(r, uV + (bOffV + ks * 16 * 72 + fp * 16) * 2u);
                uint32_t b0[2] = {r[0], r[1]};
                uint32_t b1[2] = {r[2], r[3]};
                mma_f16(accO[2 * fp], a, b0);
                mma_f16(accO[2 * fp + 1], a, b1);
            }
        }
        __syncthreads();

        {
            int vn = (it + 1 < t1) ? (it + 1) : (t1 - 1);
            load_sr(vn);
            load_v(vn);
            CP_COMMIT();
        }
    }

    const size_t base0 = ((size_t)b * HH + h) * QQ + qg0;
    const size_t base1 = base0 + 8;
    float* o0 = g_opart + (base0 * KSPLIT + split) * DHH;
    float* o1 = g_opart + (base1 * KSPLIT + split) * DHH;
#pragma unroll
    for (int fn = 0; fn < 8; fn++) {
        int col = fn * 8 + 2 * c4;
        *(float2*)(o0 + col) = make_float2(accO[fn][0], accO[fn][1]);
        *(float2*)(o1 + col) = make_float2(accO[fn][2], accO[fn][3]);
    }
    if (c4 == 0) {
        float* ml0 = g_ml + (base0 * KSPLIT + split) * 2;
        float* ml1 = g_ml + (base1 * KSPLIT + split) * 2;
        ml0[0] = m0; ml0[1] = l0;
        ml1[0] = m1; ml1[1] = l1;
    }
}

// ---------------------------------------------------------------------------
// Combine split-K partials -> ctx (fp16)
// ---------------------------------------------------------------------------
__global__ void __launch_bounds__(256) combine_kernel() {
    const int col = threadIdx.x & 63;
    const int rloc = threadIdx.x >> 6;
    const int q = blockIdx.x * 4 + rloc;
    const int h = blockIdx.y, b = blockIdx.z;
    const size_t base = ((size_t)b * HH + h) * QQ + q;

    float m[KSPLIT], l[KSPLIT];
#pragma unroll
    for (int s = 0; s < KSPLIT; s++) {
        m[s] = g_ml[(base * KSPLIT + s) * 2 + 0];
        l[s] = g_ml[(base * KSPLIT + s) * 2 + 1];
    }
    float mx = m[0];
#pragma unroll
    for (int s = 1; s < KSPLIT; s++) mx = fmaxf(mx, m[s]);
    float w[KSPLIT], L = 0.f;
#pragma unroll
    for (int s = 0; s < KSPLIT; s++) { w[s] = __expf(m[s] - mx); L += l[s] * w[s]; }
    const float inv = 1.0f / L;

    float o = 0.f;
#pragma unroll
    for (int s = 0; s < KSPLIT; s++)
        o += g_opart[(base * KSPLIT + s) * DHH + col] * w[s];
    g_ctxh[((size_t)b * QQ + q) * UU + h * 64 + col] = __float2half(o * inv);
}

// ---------------------------------------------------------------------------
// Launch
// ---------------------------------------------------------------------------
extern "C" void kernel_launch(void* const* d_in, const int* in_sizes, int n_in,
                              void* d_out, int out_size) {
    const float* inputs    = (const float*)d_in[0];
    const float* relatives = (const float*)d_in[1];
    const float* memories  = (const float*)d_in[2];
    const float* bias_c    = (const float*)d_in[3];
    const float* bias_r    = (const float*)d_in[4];
    const float* Wq        = (const float*)d_in[5];
    const float* Wkv       = (const float*)d_in[6];
    const float* Wr        = (const float*)d_in[7];
    const float* Wo        = (const float*)d_in[8];
    float* out             = (float*)d_out;

    constexpr int SMEM_G  = 4 * (128 + 128) * G_LDSS * 2;                // 81920
    constexpr int SMEM_WO = 4 * (128 + 64) * G_LDSS * 2;                 // 61440
    constexpr int SMEM_SR = 2 * (128 + 128) * G_LDSS * 2;                // 40960
    constexpr int SMEM_F  = (3 * 128 * 72 + 128 * 72 + 128 * 136) * 2;   // 108544
    cudaFuncSetAttribute((const void*)proj_kernel,
                         cudaFuncAttributeMaxDynamicSharedMemorySize, SMEM_G);
    cudaFuncSetAttribute((const void*)wo_kernel,
                         cudaFuncAttributeMaxDynamicSharedMemorySize, SMEM_WO);
    cudaFuncSetAttribute((const void*)sr_kernel,
                         cudaFuncAttributeMaxDynamicSharedMemorySize, SMEM_SR);
    cudaFuncSetAttribute((const void*)flash_kernel,
                         cudaFuncAttributeMaxDynamicSharedMemorySize, SMEM_F);

    // 0. weight transposes + fp16 prep, single launch (5120 + 16384 CTAs)
    setup_kernel<<<21504, 256>>>(memories, inputs, relatives, Wq, Wkv, Wr, Wo);

    // 1. merged projections: wkv | wr | wq  (896 CTAs, one launch)
    proj_kernel<<<896, 256, SMEM_G>>>(bias_c, bias_r);

    // 2. SrShift = shifted (qr @ wr^T), SMEM-staged coalesced store
    sr_kernel<<<dim3(KL / 128, QQ / 128, BB * HH), 256, SMEM_SR>>>();

    // 3. split-K fused fp16 flash -> partials
    flash_kernel<<<dim3(8 * KSPLIT, HH, BB), 256, SMEM_F>>>();

    // 4. combine partials -> ctx (fp16)
    combine_kernel<<<dim3(QQ / 4, HH, BB), 256>>>();

    // 5. out = ctx @ Wo (fp32 out, BN=64 for 2 CTAs/SM)
    wo_kernel<<<dim3(UU / 64, (BB * QQ) / 128, 1), 256, SMEM_WO>>>(out);
}

// round 16
// speedup vs baseline: 1.4920x; 1.0069x over previous
#include <cuda_runtime.h>
#include <cuda_fp16.h>
#include <cstdint>

// Problem constants
#define BB   2
#define QQ   1024
#define MEMN 1024
#define UU   1024
#define HH   16
#define DHH  64
#define KL   2048   // MEM + Q
#define KSPLIT 3

// score scale folded into q projections: 1/sqrt(64) * log2(e)
#define QSCALE (0.125f * 1.4426950408889634f)

// ---------------------------------------------------------------------------
// Scratch (allocation-free: __device__ globals, 16B-aligned for cp.async)
// ---------------------------------------------------------------------------
__device__ __align__(16) __half g_fullh[(size_t)BB * KL * UU];     // fp16 concat
__device__ __align__(16) __half g_relrh[(size_t)BB * KL * UU];     // fp16 relatives
__device__ __align__(16) __half g_qch [(size_t)BB * QQ * UU];      // fp16 (q+bc)*QSCALE
__device__ __align__(16) __half g_qrh [(size_t)BB * QQ * UU];      // fp16 (q+br)*QSCALE
__device__ __align__(16) __half g_kh  [(size_t)BB * KL * UU];      // fp16 K
__device__ __align__(16) __half g_vh  [(size_t)BB * KL * UU];      // fp16 V  [b,t,u]
__device__ __align__(16) __half g_wrh [(size_t)BB * KL * UU];      // fp16 w_r
__device__ __align__(16) __half g_srh [(size_t)BB * HH * QQ * KL]; // fp16 Sr SHIFTED (scaled)
__device__ __align__(16) __half g_ctxh[(size_t)BB * QQ * UU];      // fp16 attention out
__device__ __align__(16) __half g_wqTh [(size_t)UU * UU];
__device__ __align__(16) __half g_wkvTh[(size_t)2 * UU * UU];
__device__ __align__(16) __half g_wrTh [(size_t)UU * UU];
__device__ __align__(16) __half g_woTh [(size_t)UU * UU];
__device__ float g_opart[(size_t)BB * HH * QQ * KSPLIT * DHH];
__device__ float g_ml   [(size_t)BB * HH * QQ * KSPLIT * 2];   // m in log2 domain

// ---------------------------------------------------------------------------
// Helpers
// ---------------------------------------------------------------------------
__device__ __forceinline__ uint32_t smem_to_u32(const void* p) {
    uint32_t a;
    asm("{ .reg .u64 t; cvta.to.shared.u64 t, %1; cvt.u32.u64 %0, t; }" : "=r"(a) : "l"(p));
    return a;
}
__device__ __forceinline__ void cp_async16(uint32_t saddr, const void* gaddr) {
    asm volatile("cp.async.cg.shared.global [%0], [%1], 16;" :: "r"(saddr), "l"(gaddr));
}
#define CP_COMMIT() asm volatile("cp.async.commit_group;" ::: "memory")
#define CP_WAIT0()  asm volatile("cp.async.wait_group 0;" ::: "memory")
#define CP_WAIT1()  asm volatile("cp.async.wait_group 1;" ::: "memory")
#define CP_WAIT2()  asm volatile("cp.async.wait_group 2;" ::: "memory")

__device__ __forceinline__ void mma_f16(float acc[4], const uint32_t a[4], const uint32_t b[2]) {
    asm volatile("mma.sync.aligned.m16n8k16.row.col.f32.f16.f16.f32 "
        "{%0,%1,%2,%3}, {%4,%5,%6,%7}, {%8,%9}, {%0,%1,%2,%3};"
        : "+f"(acc[0]), "+f"(acc[1]), "+f"(acc[2]), "+f"(acc[3])
        : "r"(a[0]), "r"(a[1]), "r"(a[2]), "r"(a[3]), "r"(b[0]), "r"(b[1]));
}
__device__ __forceinline__ void ldsm_x4(uint32_t* r, uint32_t addr) {
    asm volatile("ldmatrix.sync.aligned.m8n8.x4.shared.b16 {%0,%1,%2,%3}, [%4];"
        : "=r"(r[0]), "=r"(r[1]), "=r"(r[2]), "=r"(r[3]) : "r"(addr));
}
__device__ __forceinline__ void ldsm_x4t(uint32_t* r, uint32_t addr) {
    asm volatile("ldmatrix.sync.aligned.m8n8.x4.trans.shared.b16 {%0,%1,%2,%3}, [%4];"
        : "=r"(r[0]), "=r"(r[1]), "=r"(r[2]), "=r"(r[3]) : "r"(addr));
}

// ---------------------------------------------------------------------------
// Fused setup: weight transposes + fp16 conversions of concat/relatives.
// Blocks [0,5120) = transposes; [5120, 21504) = prep copies.
// ---------------------------------------------------------------------------
__global__ void __launch_bounds__(256)
setup_kernel(const float* __restrict__ mem, const float* __restrict__ inp,
             const float* __restrict__ rel,
             const float* __restrict__ Wq, const float* __restrict__ Wkv,
             const float* __restrict__ Wr, const float* __restrict__ Wo) {
    const int tid = threadIdx.x;
    int bid = blockIdx.x;
    if (bid < 5120) {
        __shared__ float t[32][33];
        const float* in; __half* out; int cols;
        if (bid < 1024)      { in = Wq;  out = g_wqTh;  cols = 1024; }
        else if (bid < 3072) { in = Wkv; out = g_wkvTh; cols = 2048; bid -= 1024; }
        else if (bid < 4096) { in = Wr;  out = g_wrTh;  cols = 1024; bid -= 3072; }
        else                 { in = Wo;  out = g_woTh;  cols = 1024; bid -= 4096; }
        int tilesX = cols / 32;
        int c0 = (bid % tilesX) * 32;
        int r0 = (bid / tilesX) * 32;
        int tx = tid & 31, ty = tid >> 5;
#pragma unroll
        for (int i = 0; i < 32; i += 8)
            t[ty + i][tx] = in[(size_t)(r0 + ty + i) * cols + c0 + tx];
        __syncthreads();
#pragma unroll
        for (int i = 0; i < 32; i += 8)
            out[(size_t)(c0 + ty + i) * 1024 + r0 + tx] = __float2half(t[tx][ty + i]);
    } else {
        const size_t total4 = (size_t)BB * KL * UU / 4;
        size_t i = (size_t)(bid - 5120) * 256 + tid;
        if (i < total4) {
            size_t elem = i * 4;
            int b = (int)(elem / ((size_t)KL * UU));
            size_t rem = elem % ((size_t)KL * UU);
            int t = (int)(rem / UU);
            int u = (int)(rem % UU);
            float4 v;
            if (t < MEMN) v = *(const float4*)(mem + ((size_t)b * MEMN + t) * UU + u);
            else          v = *(const float4*)(inp + ((size_t)b * QQ + (t - MEMN)) * UU + u);
            __half2* o = (__half2*)(g_fullh + elem);
            o[0] = __floats2half2_rn(v.x, v.y);
            o[1] = __floats2half2_rn(v.z, v.w);
        } else if (i < 2 * total4) {
            size_t j = i - total4;
            float4 v = ((const float4*)rel)[j];
            __half2* o = (__half2*)(g_relrh + j * 4);
            o[0] = __floats2half2_rn(v.x, v.y);
            o[1] = __floats2half2_rn(v.z, v.w);
        }
    }
}

// ===========================================================================
// Shared GEMM constants (KC=32)
// ===========================================================================
#define G_LDSS 40
#define G_KC   32

// ---------------------------------------------------------------------------
// Merged projection GEMM: one launch covers wkv (EPI4), wr (EPI3), wq (EPI2).
// Flat grid: [0,512) wkv | [512,768) wr | [768,896) wq. 4-stage pipeline.
// EPI2 scales (acc+bias) by QSCALE (score scale + log2e fold).
// ---------------------------------------------------------------------------
__global__ void __launch_bounds__(256)
proj_kernel(const float* __restrict__ bc, const float* __restrict__ br) {
    constexpr int BM = 128, BN = 128, WM = 64, WN = 32;
    constexpr int MFRAG = WM / 16, NFRAG = WN / 8;

    int cta = blockIdx.x;
    int epi;
    const __half* A;
    const __half* Bw;
    __half *Ch = nullptr, *C2h = nullptr;
    int bm, bn;
    if (cta < 512) {               // wkv
        epi = 4;
        int bx = cta & 15, by = cta >> 4;
        A = g_fullh; Bw = g_wkvTh;
        Ch = g_vh; C2h = g_kh;
        bm = by * BM; bn = bx * BN;
    } else if (cta < 768) {        // wr
        epi = 3;
        int c = cta - 512;
        int bx = c & 7, by = c >> 3;
        A = g_relrh; Bw = g_wrTh;
        Ch = g_wrh;
        bm = by * BM; bn = bx * BN;
    } else {                       // wq
        epi = 2;
        int c = cta - 768;
        int bx = c & 7, by = (c >> 3) & 7, zz = c >> 6;
        A = g_fullh + (size_t)MEMN * UU + (size_t)zz * KL * UU;
        Bw = g_wqTh;
        Ch = g_qch + (size_t)zz * QQ * UU;
        C2h = g_qrh + (size_t)zz * QQ * UU;
        bm = by * BM; bn = bx * BN;
    }
    const int lda = UU, ldb = UU, ldc = UU;
    const int nIter = UU / G_KC;   // 32

    extern __shared__ __half smh[];
    __half* As = smh;
    __half* Bs = smh + 4 * BM * G_LDSS;
    const uint32_t sA_base = smem_to_u32(As);
    const uint32_t sB_base = smem_to_u32(Bs);

    const int tid = threadIdx.x;
    const int lane = tid & 31;
    const int warp = tid >> 5;
    const int wm = warp & 1;
    const int wn = warp >> 1;
    const __half* Ag = A + (size_t)bm * lda;
    const __half* Bg = Bw + (size_t)bn * ldb;

    auto load_stage = [&](int stage, int buf) {
#pragma unroll
        for (int i = 0; i < 2; i++) {
            int idx = tid + i * 256;
            int row = idx >> 2, ch = idx & 3;
            uint32_t s = sA_base + (uint32_t)(buf * BM * G_LDSS + row * G_LDSS + ch * 8) * 2u;
            cp_async16(s, Ag + (size_t)row * lda + stage * G_KC + ch * 8);
        }
#pragma unroll
        for (int i = 0; i < 2; i++) {
            int idx = tid + i * 256;
            int row = idx >> 2, ch = idx & 3;
            uint32_t s = sB_base + (uint32_t)(buf * BN * G_LDSS + row * G_LDSS + ch * 8) * 2u;
            cp_async16(s, Bg + (size_t)row * ldb + stage * G_KC + ch * 8);
        }
    };

    float acc[MFRAG][NFRAG][4];
#pragma unroll
    for (int i = 0; i < MFRAG; i++)
#pragma unroll
        for (int j = 0; j < NFRAG; j++)
#pragma unroll
            for (int v = 0; v < 4; v++) acc[i][j][v] = 0.0f;

    load_stage(0, 0); CP_COMMIT();
    load_stage(1, 1); CP_COMMIT();
    load_stage(2, 2); CP_COMMIT();

    const uint32_t aOff = (uint32_t)((wm * WM + (lane & 15)) * G_LDSS + (lane >> 4) * 8);
    const uint32_t bOff = (uint32_t)((wn * WN + (lane & 7) + (lane >> 4) * 8) * G_LDSS +
                                     ((lane >> 3) & 1) * 8);
    const int r4 = lane >> 2;
    const int c4 = lane & 3;

    for (int it = 0; it < nIter; ++it) {
        CP_WAIT2();
        __syncthreads();
        if (it + 3 < nIter) load_stage(it + 3, (it + 3) & 3);
        CP_COMMIT();

        const uint32_t aBuf = sA_base + (uint32_t)((it & 3) * BM * G_LDSS) * 2u;
        const uint32_t bBuf = sB_base + (uint32_t)((it & 3) * BN * G_LDSS) * 2u;

#pragma unroll
        for (int ks = 0; ks < 2; ks++) {
            uint32_t af[MFRAG][4];
            uint32_t bf[NFRAG][2];
#pragma unroll
            for (int fm = 0; fm < MFRAG; fm++)
                ldsm_x4(af[fm], aBuf + (aOff + fm * 16 * G_LDSS + ks * 16) * 2u);
#pragma unroll
            for (int fp = 0; fp < NFRAG / 2; fp++) {
                uint32_t r[4];
                ldsm_x4(r, bBuf + (bOff + fp * 16 * G_LDSS + ks * 16) * 2u);
                bf[2 * fp][0] = r[0]; bf[2 * fp][1] = r[1];
                bf[2 * fp + 1][0] = r[2]; bf[2 * fp + 1][1] = r[3];
            }
#pragma unroll
            for (int fm = 0; fm < MFRAG; fm++)
#pragma unroll
                for (int fn = 0; fn < NFRAG; fn++)
                    mma_f16(acc[fm][fn], af[fm], bf[fn]);
        }
    }

    const int m0 = bm + wm * WM;
    const int n0 = bn + wn * WN;
#pragma unroll
    for (int fm = 0; fm < MFRAG; fm++) {
#pragma unroll
        for (int fn = 0; fn < NFRAG; fn++) {
            int r = m0 + fm * 16 + r4;
            int cidx = n0 + fn * 8 + c4 * 2;
            float a0 = acc[fm][fn][0], a1 = acc[fm][fn][1];
            float a2 = acc[fm][fn][2], a3 = acc[fm][fn][3];
            if (epi == 4) {
                if (cidx < UU) {
                    *(__half2*)(C2h + (size_t)r * UU + cidx) = __floats2half2_rn(a0, a1);
                    *(__half2*)(C2h + (size_t)(r + 8) * UU + cidx) = __floats2half2_rn(a2, a3);
                } else {
                    *(__half2*)(Ch + (size_t)r * UU + cidx - UU) = __floats2half2_rn(a0, a1);
                    *(__half2*)(Ch + (size_t)(r + 8) * UU + cidx - UU) = __floats2half2_rn(a2, a3);
                }
            } else if (epi == 3) {
                *(__half2*)(Ch + (size_t)r * ldc + cidx) = __floats2half2_rn(a0, a1);
                *(__half2*)(Ch + (size_t)(r + 8) * ldc + cidx) = __floats2half2_rn(a2, a3);
            } else {  // epi == 2: scaled q projections
                float b0 = bc[cidx], b1 = bc[cidx + 1];
                float r0 = br[cidx], r1 = br[cidx + 1];
                *(__half2*)(Ch + (size_t)r * ldc + cidx) =
                    __floats2half2_rn((a0 + b0) * QSCALE, (a1 + b1) * QSCALE);
                *(__half2*)(Ch + (size_t)(r + 8) * ldc + cidx) =
                    __floats2half2_rn((a2 + b0) * QSCALE, (a3 + b1) * QSCALE);
                *(__half2*)(C2h + (size_t)r * ldc + cidx) =
                    __floats2half2_rn((a0 + r0) * QSCALE, (a1 + r1) * QSCALE);
                *(__half2*)(C2h + (size_t)(r + 8) * ldc + cidx) =
                    __floats2half2_rn((a2 + r0) * QSCALE, (a3 + r1) * QSCALE);
            }
        }
    }
}

// ---------------------------------------------------------------------------
// Sr shifted GEMM, K=64 specialized (R12 config): 2 flat K-chunks,
// SMEM-staged coalesced shifted store. Grid (KL/128, QQ/128, BB*HH).
// ---------------------------------------------------------------------------
__global__ void __launch_bounds__(256)
sr_kernel() {
    constexpr int BM = 128, BN = 128, WM = 64, WN = 32;
    constexpr int MFRAG = WM / 16, NFRAG = WN / 8;

    const int bm = blockIdx.y * BM;
    const int bn = blockIdx.x * BN;
    if (bn + bm + BM + BN - 2 - (QQ - 1) < 0) return;

    const int z = blockIdx.z;          // b*HH + h
    const int z1 = z / HH, z2 = z % HH;
    const __half* A = g_qrh + (size_t)z1 * QQ * UU + (size_t)z2 * 64;
    const __half* B = g_wrh + (size_t)z1 * KL * UU + (size_t)z2 * 64;
    __half* C = g_srh + (size_t)z * QQ * KL;

    extern __shared__ __half smh[];
    __half* As = smh;                       // [2][128][40]
    __half* Bs = smh + 2 * BM * G_LDSS;     // [2][128][40]
    const uint32_t sA_base = smem_to_u32(As);
    const uint32_t sB_base = smem_to_u32(Bs);

    const int tid = threadIdx.x;
    const int lane = tid & 31;
    const int warp = tid >> 5;
    const int wm = warp & 1;
    const int wn = warp >> 1;
    const __half* Ag = A + (size_t)bm * UU;
    const __half* Bg = B + (size_t)bn * UU;

#pragma unroll
    for (int st = 0; st < 2; st++) {
#pragma unroll
        for (int i = 0; i < 2; i++) {
            int idx = tid + i * 256;
            int row = idx >> 2, ch = idx & 3;
            cp_async16(sA_base + (uint32_t)(st * BM * G_LDSS + row * G_LDSS + ch * 8) * 2u,
                       Ag + (size_t)row * UU + st * G_KC + ch * 8);
        }
#pragma unroll
        for (int i = 0; i < 2; i++) {
            int idx = tid + i * 256;
            int row = idx >> 2, ch = idx & 3;
            cp_async16(sB_base + (uint32_t)(st * BN * G_LDSS + row * G_LDSS + ch * 8) * 2u,
                       Bg + (size_t)row * UU + st * G_KC + ch * 8);
        }
        CP_COMMIT();
    }
    CP_WAIT0();
    __syncthreads();

    const uint32_t aOff = (uint32_t)((wm * WM + (lane & 15)) * G_LDSS + (lane >> 4) * 8);
    const uint32_t bOff = (uint32_t)((wn * WN + (lane & 7) + (lane >> 4) * 8) * G_LDSS +
                                     ((lane >> 3) & 1) * 8);
    const int r4 = lane >> 2;
    const int c4 = lane & 3;

    float acc[MFRAG][NFRAG][4];
#pragma unroll
    for (int i = 0; i < MFRAG; i++)
#pragma unroll
        for (int j = 0; j < NFRAG; j++)
#pragma unroll
            for (int v = 0; v < 4; v++) acc[i][j][v] = 0.0f;

#pragma unroll
    for (int st = 0; st < 2; st++) {
        const uint32_t aBuf = sA_base + (uint32_t)(st * BM * G_LDSS) * 2u;
        const uint32_t bBuf = sB_base + (uint32_t)(st * BN * G_LDSS) * 2u;
#pragma unroll
        for (int ks = 0; ks < 2; ks++) {
            uint32_t af[MFRAG][4];
            uint32_t bf[NFRAG][2];
#pragma unroll
            for (int fm = 0; fm < MFRAG; fm++)
                ldsm_x4(af[fm], aBuf + (aOff + fm * 16 * G_LDSS + ks * 16) * 2u);
#pragma unroll
            for (int fp = 0; fp < NFRAG / 2; fp++) {
                uint32_t r[4];
                ldsm_x4(r, bBuf + (bOff + fp * 16 * G_LDSS + ks * 16) * 2u);
                bf[2 * fp][0] = r[0]; bf[2 * fp][1] = r[1];
                bf[2 * fp + 1][0] = r[2]; bf[2 * fp + 1][1] = r[3];
            }
#pragma unroll
            for (int fm = 0; fm < MFRAG; fm++)
#pragma unroll
                for (int fn = 0; fn < NFRAG; fn++)
                    mma_f16(acc[fm][fn], af[fm], bf[fn]);
        }
    }

    __syncthreads();
    __half* Cs = smh;
    const int m0l = wm * WM;
    const int n0l = wn * WN;
#pragma unroll
    for (int fm = 0; fm < MFRAG; fm++) {
#pragma unroll
        for (int fn = 0; fn < NFRAG; fn++) {
            int lr = m0l + fm * 16 + r4;
            int lc = n0l + fn * 8 + 2 * c4;
            *(__half2*)(Cs + lr * 136 + lc) =
                __floats2half2_rn(acc[fm][fn][0], acc[fm][fn][1]);
            *(__half2*)(Cs + (lr + 8) * 136 + lc) =
                __floats2half2_rn(acc[fm][fn][2], acc[fm][fn][3]);
        }
    }
    __syncthreads();

    const int col = tid & 127;
    const int off = bn - (QQ - 1) + bm;
#pragma unroll 4
    for (int r = tid >> 7; r < 128; r += 2) {
        int k = off + r + col;
        if (k >= 0)
            C[(size_t)(bm + r) * KL + k] = Cs[r * 136 + col];
    }
}

// ---------------------------------------------------------------------------
// Wo GEMM: BN=64 (WN=16) -> 256 CTAs. Grid (16, 16, 1), fp32 out.
// ---------------------------------------------------------------------------
__global__ void __launch_bounds__(256)
wo_kernel(float* __restrict__ out) {
    constexpr int BM = 128, BN = 64, WM = 64, WN = 16;
    constexpr int MFRAG = WM / 16, NFRAG = WN / 8;

    const int bm = blockIdx.y * BM;
    const int bn = blockIdx.x * BN;

    extern __shared__ __half smh[];
    __half* As = smh;
    __half* Bs = smh + 4 * BM * G_LDSS;
    const uint32_t sA_base = smem_to_u32(As);
    const uint32_t sB_base = smem_to_u32(Bs);

    const int tid = threadIdx.x;
    const int lane = tid & 31;
    const int warp = tid >> 5;
    const int wm = warp & 1;
    const int wn = warp >> 1;
    const __half* Ag = g_ctxh + (size_t)bm * UU;
    const __half* Bg = g_woTh + (size_t)bn * UU;
    const int nIter = UU / G_KC;

    auto load_stage = [&](int stage, int buf) {
#pragma unroll
        for (int i = 0; i < 2; i++) {
            int idx = tid + i * 256;
            int row = idx >> 2, ch = idx & 3;
            cp_async16(sA_base + (uint32_t)(buf * BM * G_LDSS + row * G_LDSS + ch * 8) * 2u,
                       Ag + (size_t)row * UU + stage * G_KC + ch * 8);
        }
        {
            int idx = tid;
            int row = idx >> 2, ch = idx & 3;
            cp_async16(sB_base + (uint32_t)(buf * BN * G_LDSS + row * G_LDSS + ch * 8) * 2u,
                       Bg + (size_t)row * UU + stage * G_KC + ch * 8);
        }
    };

    float acc[MFRAG][NFRAG][4];
#pragma unroll
    for (int i = 0; i < MFRAG; i++)
#pragma unroll
        for (int j = 0; j < NFRAG; j++)
#pragma unroll
            for (int v = 0; v < 4; v++) acc[i][j][v] = 0.0f;

    load_stage(0, 0); CP_COMMIT();
    load_stage(1, 1); CP_COMMIT();
    load_stage(2, 2); CP_COMMIT();

    const uint32_t aOff = (uint32_t)((wm * WM + (lane & 15)) * G_LDSS + (lane >> 4) * 8);
    const uint32_t bOff = (uint32_t)((wn * WN + (lane & 7) + (lane >> 4) * 8) * G_LDSS +
                                     ((lane >> 3) & 1) * 8);
    const int r4 = lane >> 2;
    const int c4 = lane & 3;

    for (int it = 0; it < nIter; ++it) {
        CP_WAIT2();
        __syncthreads();
        if (it + 3 < nIter) load_stage(it + 3, (it + 3) & 3);
        CP_COMMIT();

        const uint32_t aBuf = sA_base + (uint32_t)((it & 3) * BM * G_LDSS) * 2u;
        const uint32_t bBuf = sB_base + (uint32_t)((it & 3) * BN * G_LDSS) * 2u;

#pragma unroll
        for (int ks = 0; ks < 2; ks++) {
            uint32_t af[MFRAG][4];
            uint32_t bf[NFRAG][2];
#pragma unroll
            for (int fm = 0; fm < MFRAG; fm++)
                ldsm_x4(af[fm], aBuf + (aOff + fm * 16 * G_LDSS + ks * 16) * 2u);
            {
                uint32_t r[4];
                ldsm_x4(r, bBuf + (bOff + ks * 16) * 2u);
                bf[0][0] = r[0]; bf[0][1] = r[1];
                bf[1][0] = r[2]; bf[1][1] = r[3];
            }
#pragma unroll
            for (int fm = 0; fm < MFRAG; fm++)
#pragma unroll
                for (int fn = 0; fn < NFRAG; fn++)
                    mma_f16(acc[fm][fn], af[fm], bf[fn]);
        }
    }

    const int m0 = bm + wm * WM;
    const int n0 = bn + wn * WN;
#pragma unroll
    for (int fm = 0; fm < MFRAG; fm++) {
#pragma unroll
        for (int fn = 0; fn < NFRAG; fn++) {
            int r = m0 + fm * 16 + r4;
            int cidx = n0 + fn * 8 + c4 * 2;
            *(float2*)(out + (size_t)r * UU + cidx) =
                make_float2(acc[fm][fn][0], acc[fm][fn][1]);
            *(float2*)(out + (size_t)(r + 8) * UU + cidx) =
                make_float2(acc[fm][fn][2], acc[fm][fn][3]);
        }
    }
}

// ---------------------------------------------------------------------------
// Split-K fused fp16 flash attention. Scores arrive pre-scaled in log2 domain;
// P = exp2(s-m) via h2exp2 (fp16x2 MUFU). m/l stored in log2 domain.
// Grid (8*KSPLIT, H, B), 256 threads, 2 CTAs/SM.
// ---------------------------------------------------------------------------
__global__ void __launch_bounds__(256, 2) flash_kernel() {
    extern __shared__ __half smh[];
    __half* sQ  = smh;                  // [128][72]
    __half* sKa = sQ  + 128 * 72;
    __half* sKb = sKa + 128 * 72;
    __half* sV  = sKb + 128 * 72;       // [128 t][72 d]
    __half* sP  = sV  + 128 * 72;       // [128][136]
    const uint32_t uQ  = smem_to_u32(sQ);
    const uint32_t uKa = smem_to_u32(sKa);
    const uint32_t uKb = smem_to_u32(sKb);
    const uint32_t uV  = smem_to_u32(sV);
    const uint32_t uP  = smem_to_u32(sP);

    const int tid = threadIdx.x, lane = tid & 31, warp = tid >> 5;
    const int r4 = lane >> 2, c4 = lane & 3;
    const int qs = (int)blockIdx.x;
    const int qt = 7 - (qs / KSPLIT);
    const int split = qs % KSPLIT;
    const int h = blockIdx.y, b = blockIdx.z;
    const int q0 = qt * 128;
    const int nT = 9 + qt;
    const int t0 = (split * nT) / KSPLIT;
    const int t1 = ((split + 1) * nT) / KSPLIT;

    const __half* gQ = g_qch + ((size_t)b * QQ + q0) * UU + h * 64;
    const __half* gK = g_kh  + (size_t)b * KL * UU + h * 64;
    const __half* gV = g_vh  + (size_t)b * KL * UU + h * 64;
    const __half* gS = g_srh + (((size_t)b * HH + h) * QQ + q0) * KL;

    auto load_k = [&](int t, uint32_t dK) {
        const __half* src = gK + (size_t)t * 128 * UU;
        int i = tid;
#pragma unroll
        for (int rep = 0; rep < 4; rep++, i += 256) {
            int r = i >> 3, c = i & 7;
            cp_async16(dK + (uint32_t)(r * 72 + c * 8) * 2u, src + (size_t)r * UU + c * 8);
        }
    };
    auto load_v = [&](int t) {
        const __half* src = gV + (size_t)t * 128 * UU;
        int i = tid;
#pragma unroll
        for (int rep = 0; rep < 4; rep++, i += 256) {
            int r = i >> 3, c = i & 7;
            cp_async16(uV + (uint32_t)(r * 72 + c * 8) * 2u, src + (size_t)r * UU + c * 8);
        }
    };
    auto load_sr = [&](int t) {
        const __half* src = gS + (size_t)t * 128;
        int i = tid;
#pragma unroll
        for (int rep = 0; rep < 8; rep++, i += 256) {
            int r = i >> 4, c = i & 15;
            cp_async16(uP + (uint32_t)(r * 136 + c * 8) * 2u, src + (size_t)r * KL + c * 8);
        }
    };

    {
        int i = tid;
#pragma unroll
        for (int rep = 0; rep < 4; rep++, i += 256) {
            int r = i >> 3, c = i & 7;
            cp_async16(uQ + (uint32_t)(r * 72 + c * 8) * 2u, gQ + (size_t)r * UU + c * 8);
        }
        load_k(t0, uKa);
        CP_COMMIT();
        load_sr(t0);
        load_v(t0);
        CP_COMMIT();
    }

    const int lr0 = warp * 16 + r4;
    const int qg0 = q0 + lr0, qg1 = qg0 + 8;

    const uint32_t aOffQ = (uint32_t)((warp * 16 + (lane & 15)) * 72 + (lane >> 4) * 8);
    const uint32_t aOffP = (uint32_t)((warp * 16 + (lane & 15)) * 136 + (lane >> 4) * 8);
    const uint32_t bOffK = (uint32_t)(((lane & 7) + (lane >> 4) * 8) * 72 + ((lane >> 3) & 1) * 8);
    const uint32_t bOffV = (uint32_t)((lane & 15) * 72 + (lane >> 4) * 8);

    float m0 = -1e30f, m1 = -1e30f, l0 = 0.f, l1 = 0.f;
    float accO[8][4];
#pragma unroll
    for (int f = 0; f < 8; f++)
#pragma unroll
        for (int v = 0; v < 4; v++) accO[f][v] = 0.f;

    for (int it = t0; it < t1; ++it) {
        const int li = it - t0;
        const uint32_t uK = (li & 1) ? uKb : uKa;
        CP_WAIT1();
        __syncthreads();

        float accS[16][4];
#pragma unroll
        for (int f = 0; f < 16; f++)
#pragma unroll
            for (int v = 0; v < 4; v++) accS[f][v] = 0.f;
#pragma unroll
        for (int ks = 0; ks < 4; ks++) {
            uint32_t a[4];
            ldsm_x4(a, uQ + (aOffQ + ks * 16) * 2u);
#pragma unroll
            for (int fp = 0; fp < 8; fp++) {
                uint32_t r[4];
                ldsm_x4(r, uK + (bOffK + fp * 16 * 72 + ks * 16) * 2u);
                uint32_t b0[2] = {r[0], r[1]};
                uint32_t b1[2] = {r[2], r[3]};
                mma_f16(accS[2 * fp], a, b0);
                mma_f16(accS[2 * fp + 1], a, b1);
            }
        }

        {
            int kn = (it + 1 < t1) ? (it + 1) : (t1 - 1);
            load_k(kn, ((li + 1) & 1) ? uKb : uKa);
            CP_COMMIT();
        }

        CP_WAIT1();
        __syncthreads();

        const int k0 = it * 128;
        const bool lastT = (it == nT - 1);
        const int lim0 = MEMN + qg0 - k0;
        const int lim1 = lim0 + 8;

        __half* p0 = sP + lr0 * 136;
        __half* p1 = p0 + 8 * 136;

        float rm0 = -1e30f, rm1 = -1e30f;
#pragma unroll
        for (int fn = 0; fn < 16; fn++) {
            int kc = fn * 8 + 2 * c4;
            float2 f0 = __half22float2(*(const __half2*)(p0 + kc));
            float2 f1 = __half22float2(*(const __half2*)(p1 + kc));
            float s0, s1, s2, s3;
            s0 = (!lastT || kc     <= lim0) ? (accS[fn][0] + f0.x) : -1e30f;
            s1 = (!lastT || kc + 1 <= lim0) ? (accS[fn][1] + f0.y) : -1e30f;
            s2 = (!lastT || kc     <= lim1) ? (accS[fn][2] + f1.x) : -1e30f;
            s3 = (!lastT || kc + 1 <= lim1) ? (accS[fn][3] + f1.y) : -1e30f;
            accS[fn][0] = s0; accS[fn][1] = s1; accS[fn][2] = s2; accS[fn][3] = s3;
            rm0 = fmaxf(rm0, fmaxf(s0, s1));
            rm1 = fmaxf(rm1, fmaxf(s2, s3));
        }
        rm0 = fmaxf(rm0, __shfl_xor_sync(~0u, rm0, 1));
        rm0 = fmaxf(rm0, __shfl_xor_sync(~0u, rm0, 2));
        rm1 = fmaxf(rm1, __shfl_xor_sync(~0u, rm1, 1));
        rm1 = fmaxf(rm1, __shfl_xor_sync(~0u, rm1, 2));
        float mN0 = fmaxf(m0, rm0), mN1 = fmaxf(m1, rm1);
        float al0 = exp2f(m0 - mN0), al1 = exp2f(m1 - mN1);
        m0 = mN0; m1 = mN1;

        float ps0 = 0.f, ps1 = 0.f;
#pragma unroll
        for (int fn = 0; fn < 16; fn++) {
            int kc = fn * 8 + 2 * c4;
            __half2 hp0 = h2exp2(__floats2half2_rn(accS[fn][0] - m0, accS[fn][1] - m0));
            __half2 hp1 = h2exp2(__floats2half2_rn(accS[fn][2] - m1, accS[fn][3] - m1));
            float2 e0 = __half22float2(hp0);
            float2 e1 = __half22float2(hp1);
            ps0 += e0.x + e0.y;
            ps1 += e1.x + e1.y;
            *(__half2*)(p0 + kc) = hp0;
            *(__half2*)(p1 + kc) = hp1;
        }
        ps0 += __shfl_xor_sync(~0u, ps0, 1); ps0 += __shfl_xor_sync(~0u, ps0, 2);
        ps1 += __shfl_xor_sync(~0u, ps1, 1); ps1 += __shfl_xor_sync(~0u, ps1, 2);
        l0 = l0 * al0 + ps0;
        l1 = l1 * al1 + ps1;
#pragma unroll
        for (int f = 0; f < 8; f++) {
            accO[f][0] *= al0; accO[f][1] *= al0;
            accO[f][2] *= al1; accO[f][3] *= al1;
        }
        __syncwarp();

#pragma unroll
        for (int ks = 0; ks < 8; ks++) {
            uint32_t a[4];
            ldsm_x4(a, uP + (aOffP + ks * 16) * 2u);
#pragma unroll
            for (int fp = 0; fp < 4; fp++) {
                uint32_t r[4];
                ldsm_x4t(r, uV + (bOffV + ks * 16 * 72 + fp * 16) * 2u);
                uint32_t b0[2] = {r[0], r[1]};
                uint32_t b1[2] = {r[2], r[3]};
                mma_f16(accO[2 * fp], a, b0);
                mma_f16(accO[2 * fp + 1], a, b1);
            }
        }
        __syncthreads();

        {
            int vn = (it + 1 < t1) ? (it + 1) : (t1 - 1);
            load_sr(vn);
            load_v(vn);
            CP_COMMIT();
        }
    }

    const size_t base0 = ((size_t)b * HH + h) * QQ + qg0;
    const size_t base1 = base0 + 8;
    float* o0 = g_opart + (base0 * KSPLIT + split) * DHH;
    float* o1 = g_opart + (base1 * KSPLIT + split) * DHH;
#pragma unroll
    for (int fn = 0; fn < 8; fn++) {
        int col = fn * 8 + 2 * c4;
        *(float2*)(o0 + col) = make_float2(accO[fn][0], accO[fn][1]);
        *(float2*)(o1 + col) = make_float2(accO[fn][2], accO[fn][3]);
    }
    if (c4 == 0) {
        float* ml0 = g_ml + (base0 * KSPLIT + split) * 2;
        float* ml1 = g_ml + (base1 * KSPLIT + split) * 2;
        ml0[0] = m0; ml0[1] = l0;
        ml1[0] = m1; ml1[1] = l1;
    }
}

// ---------------------------------------------------------------------------
// Combine split-K partials -> ctx (fp16). m values are in log2 domain.
// ---------------------------------------------------------------------------
__global__ void __launch_bounds__(256) combine_kernel() {
    const int col = threadIdx.x & 63;
    const int rloc = threadIdx.x >> 6;
    const int q = blockIdx.x * 4 + rloc;
    const int h = blockIdx.y, b = blockIdx.z;
    const size_t base = ((size_t)b * HH + h) * QQ + q;

    float m[KSPLIT], l[KSPLIT];
#pragma unroll
    for (int s = 0; s < KSPLIT; s++) {
        m[s] = g_ml[(base * KSPLIT + s) * 2 + 0];
        l[s] = g_ml[(base * KSPLIT + s) * 2 + 1];
    }
    float mx = m[0];
#pragma unroll
    for (int s = 1; s < KSPLIT; s++) mx = fmaxf(mx, m[s]);
    float w[KSPLIT], L = 0.f;
#pragma unroll
    for (int s = 0; s < KSPLIT; s++) { w[s] = exp2f(m[s] - mx); L += l[s] * w[s]; }
    const float inv = 1.0f / L;

    float o = 0.f;
#pragma unroll
    for (int s = 0; s < KSPLIT; s++)
        o += g_opart[(base * KSPLIT + s) * DHH + col] * w[s];
    g_ctxh[((size_t)b * QQ + q) * UU + h * 64 + col] = __float2half(o * inv);
}

// ---------------------------------------------------------------------------
// Launch
// ---------------------------------------------------------------------------
extern "C" void kernel_launch(void* const* d_in, const int* in_sizes, int n_in,
                              void* d_out, int out_size) {
    const float* inputs    = (const float*)d_in[0];
    const float* relatives = (const float*)d_in[1];
    const float* memories  = (const float*)d_in[2];
    const float* bias_c    = (const float*)d_in[3];
    const float* bias_r    = (const float*)d_in[4];
    const float* Wq        = (const float*)d_in[5];
    const float* Wkv       = (const float*)d_in[6];
    const float* Wr        = (const float*)d_in[7];
    const float* Wo        = (const float*)d_in[8];
    float* out             = (float*)d_out;

    constexpr int SMEM_G  = 4 * (128 + 128) * G_LDSS * 2;                // 81920
    constexpr int SMEM_WO = 4 * (128 + 64) * G_LDSS * 2;                 // 61440
    constexpr int SMEM_SR = 2 * (128 + 128) * G_LDSS * 2;                // 40960
    constexpr int SMEM_F  = (3 * 128 * 72 + 128 * 72 + 128 * 136) * 2;   // 108544
    cudaFuncSetAttribute((const void*)proj_kernel,
                         cudaFuncAttributeMaxDynamicSharedMemorySize, SMEM_G);
    cudaFuncSetAttribute((const void*)wo_kernel,
                         cudaFuncAttributeMaxDynamicSharedMemorySize, SMEM_WO);
    cudaFuncSetAttribute((const void*)sr_kernel,
                         cudaFuncAttributeMaxDynamicSharedMemorySize, SMEM_SR);
    cudaFuncSetAttribute((const void*)flash_kernel,
                         cudaFuncAttributeMaxDynamicSharedMemorySize, SMEM_F);

    // 0. weight transposes + fp16 prep, single launch
    setup_kernel<<<21504, 256>>>(memories, inputs, relatives, Wq, Wkv, Wr, Wo);

    // 1. merged projections: wkv | wr | wq  (896 CTAs, one launch)
    proj_kernel<<<896, 256, SMEM_G>>>(bias_c, bias_r);

    // 2. SrShift = shifted (qr @ wr^T) — pre-scaled via qr
    sr_kernel<<<dim3(KL / 128, QQ / 128, BB * HH), 256, SMEM_SR>>>();

    // 3. split-K fused fp16 flash (log2-domain softmax) -> partials
    flash_kernel<<<dim3(8 * KSPLIT, HH, BB), 256, SMEM_F>>>();

    // 4. combine partials -> ctx (fp16)
    combine_kernel<<<dim3(QQ / 4, HH, BB), 256>>>();

    // 5. out = ctx @ Wo (fp32 out)
    wo_kernel<<<dim3(UU / 64, (BB * QQ) / 128, 1), 256, SMEM_WO>>>(out);
}

// round 17
// speedup vs baseline: 1.5319x; 1.0267x over previous
#include <cuda_runtime.h>
#include <cuda_fp16.h>
#include <cstdint>

// Problem constants
#define BB   2
#define QQ   1024
#define MEMN 1024
#define UU   1024
#define HH   16
#define DHH  64
#define KL   2048   // MEM + Q
#define KSPLIT 3

// score scale folded into q projections: 1/sqrt(64) * log2(e)
#define QSCALE (0.125f * 1.4426950408889634f)

// ---------------------------------------------------------------------------
// Scratch (allocation-free: __device__ globals, 16B-aligned for cp.async)
// ---------------------------------------------------------------------------
__device__ __align__(16) __half g_fullh[(size_t)BB * KL * UU];     // fp16 concat
__device__ __align__(16) __half g_relrh[(size_t)BB * KL * UU];     // fp16 relatives
__device__ __align__(16) __half g_qch [(size_t)BB * QQ * UU];      // fp16 (q+bc)*QSCALE
__device__ __align__(16) __half g_qrh [(size_t)BB * QQ * UU];      // fp16 (q+br)*QSCALE
__device__ __align__(16) __half g_kh  [(size_t)BB * KL * UU];      // fp16 K
__device__ __align__(16) __half g_vh  [(size_t)BB * KL * UU];      // fp16 V  [b,t,u]
__device__ __align__(16) __half g_wrh [(size_t)BB * KL * UU];      // fp16 w_r
__device__ __align__(16) __half g_srh [(size_t)BB * HH * QQ * KL]; // fp16 Sr SHIFTED (scaled)
__device__ __align__(16) __half g_ctxh[(size_t)BB * QQ * UU];      // fp16 attention out
__device__ __align__(16) __half g_wqTh [(size_t)UU * UU];
__device__ __align__(16) __half g_wkvTh[(size_t)2 * UU * UU];
__device__ __align__(16) __half g_wrTh [(size_t)UU * UU];
__device__ __align__(16) __half g_woTh [(size_t)UU * UU];
__device__ float g_opart[(size_t)BB * HH * QQ * KSPLIT * DHH];
__device__ float g_ml   [(size_t)BB * HH * QQ * KSPLIT * 2];   // m in log2 domain

// ---------------------------------------------------------------------------
// Helpers
// ---------------------------------------------------------------------------
__device__ __forceinline__ uint32_t smem_to_u32(const void* p) {
    uint32_t a;
    asm("{ .reg .u64 t; cvta.to.shared.u64 t, %1; cvt.u32.u64 %0, t; }" : "=r"(a) : "l"(p));
    return a;
}
__device__ __forceinline__ void cp_async16(uint32_t saddr, const void* gaddr) {
    asm volatile("cp.async.cg.shared.global [%0], [%1], 16;" :: "r"(saddr), "l"(gaddr));
}
#define CP_COMMIT() asm volatile("cp.async.commit_group;" ::: "memory")
#define CP_WAIT0()  asm volatile("cp.async.wait_group 0;" ::: "memory")
#define CP_WAIT1()  asm volatile("cp.async.wait_group 1;" ::: "memory")
#define CP_WAIT2()  asm volatile("cp.async.wait_group 2;" ::: "memory")

__device__ __forceinline__ void mma_f16(float acc[4], const uint32_t a[4], const uint32_t b[2]) {
    asm volatile("mma.sync.aligned.m16n8k16.row.col.f32.f16.f16.f32 "
        "{%0,%1,%2,%3}, {%4,%5,%6,%7}, {%8,%9}, {%0,%1,%2,%3};"
        : "+f"(acc[0]), "+f"(acc[1]), "+f"(acc[2]), "+f"(acc[3])
        : "r"(a[0]), "r"(a[1]), "r"(a[2]), "r"(a[3]), "r"(b[0]), "r"(b[1]));
}
__device__ __forceinline__ void ldsm_x4(uint32_t* r, uint32_t addr) {
    asm volatile("ldmatrix.sync.aligned.m8n8.x4.shared.b16 {%0,%1,%2,%3}, [%4];"
        : "=r"(r[0]), "=r"(r[1]), "=r"(r[2]), "=r"(r[3]) : "r"(addr));
}
__device__ __forceinline__ void ldsm_x4t(uint32_t* r, uint32_t addr) {
    asm volatile("ldmatrix.sync.aligned.m8n8.x4.trans.shared.b16 {%0,%1,%2,%3}, [%4];"
        : "=r"(r[0]), "=r"(r[1]), "=r"(r[2]), "=r"(r[3]) : "r"(addr));
}

// ---------------------------------------------------------------------------
// Fused setup: weight transposes + fp16 conversions of concat/relatives.
// Blocks [0,5120) = transposes; [5120, 21504) = prep copies.
// ---------------------------------------------------------------------------
__global__ void __launch_bounds__(256)
setup_kernel(const float* __restrict__ mem, const float* __restrict__ inp,
             const float* __restrict__ rel,
             const float* __restrict__ Wq, const float* __restrict__ Wkv,
             const float* __restrict__ Wr, const float* __restrict__ Wo) {
    const int tid = threadIdx.x;
    int bid = blockIdx.x;
    if (bid < 5120) {
        __shared__ float t[32][33];
        const float* in; __half* out; int cols;
        if (bid < 1024)      { in = Wq;  out = g_wqTh;  cols = 1024; }
        else if (bid < 3072) { in = Wkv; out = g_wkvTh; cols = 2048; bid -= 1024; }
        else if (bid < 4096) { in = Wr;  out = g_wrTh;  cols = 1024; bid -= 3072; }
        else                 { in = Wo;  out = g_woTh;  cols = 1024; bid -= 4096; }
        int tilesX = cols / 32;
        int c0 = (bid % tilesX) * 32;
        int r0 = (bid / tilesX) * 32;
        int tx = tid & 31, ty = tid >> 5;
#pragma unroll
        for (int i = 0; i < 32; i += 8)
            t[ty + i][tx] = in[(size_t)(r0 + ty + i) * cols + c0 + tx];
        __syncthreads();
#pragma unroll
        for (int i = 0; i < 32; i += 8)
            out[(size_t)(c0 + ty + i) * 1024 + r0 + tx] = __float2half(t[tx][ty + i]);
    } else {
        const size_t total4 = (size_t)BB * KL * UU / 4;
        size_t i = (size_t)(bid - 5120) * 256 + tid;
        if (i < total4) {
            size_t elem = i * 4;
            int b = (int)(elem / ((size_t)KL * UU));
            size_t rem = elem % ((size_t)KL * UU);
            int t = (int)(rem / UU);
            int u = (int)(rem % UU);
            float4 v;
            if (t < MEMN) v = *(const float4*)(mem + ((size_t)b * MEMN + t) * UU + u);
            else          v = *(const float4*)(inp + ((size_t)b * QQ + (t - MEMN)) * UU + u);
            __half2* o = (__half2*)(g_fullh + elem);
            o[0] = __floats2half2_rn(v.x, v.y);
            o[1] = __floats2half2_rn(v.z, v.w);
        } else if (i < 2 * total4) {
            size_t j = i - total4;
            float4 v = ((const float4*)rel)[j];
            __half2* o = (__half2*)(g_relrh + j * 4);
            o[0] = __floats2half2_rn(v.x, v.y);
            o[1] = __floats2half2_rn(v.z, v.w);
        }
    }
}

// ===========================================================================
// Shared GEMM constants (KC=32)
// ===========================================================================
#define G_LDSS 40
#define G_KC   32

// ---------------------------------------------------------------------------
// Merged projection GEMM: one launch covers wkv (EPI4), wr (EPI3), wq (EPI2).
// Flat grid: [0,512) wkv | [512,768) wr | [768,896) wq. 4-stage pipeline.
// EPI2 scales (acc+bias) by QSCALE (score scale + log2e fold).
// ---------------------------------------------------------------------------
__global__ void __launch_bounds__(256)
proj_kernel(const float* __restrict__ bc, const float* __restrict__ br) {
    constexpr int BM = 128, BN = 128, WM = 64, WN = 32;
    constexpr int MFRAG = WM / 16, NFRAG = WN / 8;

    int cta = blockIdx.x;
    int epi;
    const __half* A;
    const __half* Bw;
    __half *Ch = nullptr, *C2h = nullptr;
    int bm, bn;
    if (cta < 512) {               // wkv
        epi = 4;
        int bx = cta & 15, by = cta >> 4;
        A = g_fullh; Bw = g_wkvTh;
        Ch = g_vh; C2h = g_kh;
        bm = by * BM; bn = bx * BN;
    } else if (cta < 768) {        // wr
        epi = 3;
        int c = cta - 512;
        int bx = c & 7, by = c >> 3;
        A = g_relrh; Bw = g_wrTh;
        Ch = g_wrh;
        bm = by * BM; bn = bx * BN;
    } else {                       // wq
        epi = 2;
        int c = cta - 768;
        int bx = c & 7, by = (c >> 3) & 7, zz = c >> 6;
        A = g_fullh + (size_t)MEMN * UU + (size_t)zz * KL * UU;
        Bw = g_wqTh;
        Ch = g_qch + (size_t)zz * QQ * UU;
        C2h = g_qrh + (size_t)zz * QQ * UU;
        bm = by * BM; bn = bx * BN;
    }
    const int lda = UU, ldb = UU, ldc = UU;
    const int nIter = UU / G_KC;   // 32

    extern __shared__ __half smh[];
    __half* As = smh;
    __half* Bs = smh + 4 * BM * G_LDSS;
    const uint32_t sA_base = smem_to_u32(As);
    const uint32_t sB_base = smem_to_u32(Bs);

    const int tid = threadIdx.x;
    const int lane = tid & 31;
    const int warp = tid >> 5;
    const int wm = warp & 1;
    const int wn = warp >> 1;
    const __half* Ag = A + (size_t)bm * lda;
    const __half* Bg = Bw + (size_t)bn * ldb;

    auto load_stage = [&](int stage, int buf) {
#pragma unroll
        for (int i = 0; i < 2; i++) {
            int idx = tid + i * 256;
            int row = idx >> 2, ch = idx & 3;
            uint32_t s = sA_base + (uint32_t)(buf * BM * G_LDSS + row * G_LDSS + ch * 8) * 2u;
            cp_async16(s, Ag + (size_t)row * lda + stage * G_KC + ch * 8);
        }
#pragma unroll
        for (int i = 0; i < 2; i++) {
            int idx = tid + i * 256;
            int row = idx >> 2, ch = idx & 3;
            uint32_t s = sB_base + (uint32_t)(buf * BN * G_LDSS + row * G_LDSS + ch * 8) * 2u;
            cp_async16(s, Bg + (size_t)row * ldb + stage * G_KC + ch * 8);
        }
    };

    float acc[MFRAG][NFRAG][4];
#pragma unroll
    for (int i = 0; i < MFRAG; i++)
#pragma unroll
        for (int j = 0; j < NFRAG; j++)
#pragma unroll
            for (int v = 0; v < 4; v++) acc[i][j][v] = 0.0f;

    load_stage(0, 0); CP_COMMIT();
    load_stage(1, 1); CP_COMMIT();
    load_stage(2, 2); CP_COMMIT();

    const uint32_t aOff = (uint32_t)((wm * WM + (lane & 15)) * G_LDSS + (lane >> 4) * 8);
    const uint32_t bOff = (uint32_t)((wn * WN + (lane & 7) + (lane >> 4) * 8) * G_LDSS +
                                     ((lane >> 3) & 1) * 8);
    const int r4 = lane >> 2;
    const int c4 = lane & 3;

    for (int it = 0; it < nIter; ++it) {
        CP_WAIT2();
        __syncthreads();
        if (it + 3 < nIter) load_stage(it + 3, (it + 3) & 3);
        CP_COMMIT();

        const uint32_t aBuf = sA_base + (uint32_t)((it & 3) * BM * G_LDSS) * 2u;
        const uint32_t bBuf = sB_base + (uint32_t)((it & 3) * BN * G_LDSS) * 2u;

#pragma unroll
        for (int ks = 0; ks < 2; ks++) {
            uint32_t af[MFRAG][4];
            uint32_t bf[NFRAG][2];
#pragma unroll
            for (int fm = 0; fm < MFRAG; fm++)
                ldsm_x4(af[fm], aBuf + (aOff + fm * 16 * G_LDSS + ks * 16) * 2u);
#pragma unroll
            for (int fp = 0; fp < NFRAG / 2; fp++) {
                uint32_t r[4];
                ldsm_x4(r, bBuf + (bOff + fp * 16 * G_LDSS + ks * 16) * 2u);
                bf[2 * fp][0] = r[0]; bf[2 * fp][1] = r[1];
                bf[2 * fp + 1][0] = r[2]; bf[2 * fp + 1][1] = r[3];
            }
#pragma unroll
            for (int fm = 0; fm < MFRAG; fm++)
#pragma unroll
                for (int fn = 0; fn < NFRAG; fn++)
                    mma_f16(acc[fm][fn], af[fm], bf[fn]);
        }
    }

    const int m0 = bm + wm * WM;
    const int n0 = bn + wn * WN;
#pragma unroll
    for (int fm = 0; fm < MFRAG; fm++) {
#pragma unroll
        for (int fn = 0; fn < NFRAG; fn++) {
            int r = m0 + fm * 16 + r4;
            int cidx = n0 + fn * 8 + c4 * 2;
            float a0 = acc[fm][fn][0], a1 = acc[fm][fn][1];
            float a2 = acc[fm][fn][2], a3 = acc[fm][fn][3];
            if (epi == 4) {
                if (cidx < UU) {
                    *(__half2*)(C2h + (size_t)r * UU + cidx) = __floats2half2_rn(a0, a1);
                    *(__half2*)(C2h + (size_t)(r + 8) * UU + cidx) = __floats2half2_rn(a2, a3);
                } else {
                    *(__half2*)(Ch + (size_t)r * UU + cidx - UU) = __floats2half2_rn(a0, a1);
                    *(__half2*)(Ch + (size_t)(r + 8) * UU + cidx - UU) = __floats2half2_rn(a2, a3);
                }
            } else if (epi == 3) {
                *(__half2*)(Ch + (size_t)r * ldc + cidx) = __floats2half2_rn(a0, a1);
                *(__half2*)(Ch + (size_t)(r + 8) * ldc + cidx) = __floats2half2_rn(a2, a3);
            } else {  // epi == 2: scaled q projections
                float b0 = bc[cidx], b1 = bc[cidx + 1];
                float r0 = br[cidx], r1 = br[cidx + 1];
                *(__half2*)(Ch + (size_t)r * ldc + cidx) =
                    __floats2half2_rn((a0 + b0) * QSCALE, (a1 + b1) * QSCALE);
                *(__half2*)(Ch + (size_t)(r + 8) * ldc + cidx) =
                    __floats2half2_rn((a2 + b0) * QSCALE, (a3 + b1) * QSCALE);
                *(__half2*)(C2h + (size_t)r * ldc + cidx) =
                    __floats2half2_rn((a0 + r0) * QSCALE, (a1 + r1) * QSCALE);
                *(__half2*)(C2h + (size_t)(r + 8) * ldc + cidx) =
                    __floats2half2_rn((a2 + r0) * QSCALE, (a3 + r1) * QSCALE);
            }
        }
    }
}

// ---------------------------------------------------------------------------
// Sr shifted GEMM, K=64 specialized (R12 config): 2 flat K-chunks,
// SMEM-staged coalesced shifted store. Grid (KL/128, QQ/128, BB*HH).
// ---------------------------------------------------------------------------
__global__ void __launch_bounds__(256)
sr_kernel() {
    constexpr int BM = 128, BN = 128, WM = 64, WN = 32;
    constexpr int MFRAG = WM / 16, NFRAG = WN / 8;

    const int bm = blockIdx.y * BM;
    const int bn = blockIdx.x * BN;
    if (bn + bm + BM + BN - 2 - (QQ - 1) < 0) return;

    const int z = blockIdx.z;          // b*HH + h
    const int z1 = z / HH, z2 = z % HH;
    const __half* A = g_qrh + (size_t)z1 * QQ * UU + (size_t)z2 * 64;
    const __half* B = g_wrh + (size_t)z1 * KL * UU + (size_t)z2 * 64;
    __half* C = g_srh + (size_t)z * QQ * KL;

    extern __shared__ __half smh[];
    __half* As = smh;                       // [2][128][40]
    __half* Bs = smh + 2 * BM * G_LDSS;     // [2][128][40]
    const uint32_t sA_base = smem_to_u32(As);
    const uint32_t sB_base = smem_to_u32(Bs);

    const int tid = threadIdx.x;
    const int lane = tid & 31;
    const int warp = tid >> 5;
    const int wm = warp & 1;
    const int wn = warp >> 1;
    const __half* Ag = A + (size_t)bm * UU;
    const __half* Bg = B + (size_t)bn * UU;

#pragma unroll
    for (int st = 0; st < 2; st++) {
#pragma unroll
        for (int i = 0; i < 2; i++) {
            int idx = tid + i * 256;
            int row = idx >> 2, ch = idx & 3;
            cp_async16(sA_base + (uint32_t)(st * BM * G_LDSS + row * G_LDSS + ch * 8) * 2u,
                       Ag + (size_t)row * UU + st * G_KC + ch * 8);
        }
#pragma unroll
        for (int i = 0; i < 2; i++) {
            int idx = tid + i * 256;
            int row = idx >> 2, ch = idx & 3;
            cp_async16(sB_base + (uint32_t)(st * BN * G_LDSS + row * G_LDSS + ch * 8) * 2u,
                       Bg + (size_t)row * UU + st * G_KC + ch * 8);
        }
        CP_COMMIT();
    }
    CP_WAIT0();
    __syncthreads();

    const uint32_t aOff = (uint32_t)((wm * WM + (lane & 15)) * G_LDSS + (lane >> 4) * 8);
    const uint32_t bOff = (uint32_t)((wn * WN + (lane & 7) + (lane >> 4) * 8) * G_LDSS +
                                     ((lane >> 3) & 1) * 8);
    const int r4 = lane >> 2;
    const int c4 = lane & 3;

    float acc[MFRAG][NFRAG][4];
#pragma unroll
    for (int i = 0; i < MFRAG; i++)
#pragma unroll
        for (int j = 0; j < NFRAG; j++)
#pragma unroll
            for (int v = 0; v < 4; v++) acc[i][j][v] = 0.0f;

#pragma unroll
    for (int st = 0; st < 2; st++) {
        const uint32_t aBuf = sA_base + (uint32_t)(st * BM * G_LDSS) * 2u;
        const uint32_t bBuf = sB_base + (uint32_t)(st * BN * G_LDSS) * 2u;
#pragma unroll
        for (int ks = 0; ks < 2; ks++) {
            uint32_t af[MFRAG][4];
            uint32_t bf[NFRAG][2];
#pragma unroll
            for (int fm = 0; fm < MFRAG; fm++)
                ldsm_x4(af[fm], aBuf + (aOff + fm * 16 * G_LDSS + ks * 16) * 2u);
#pragma unroll
            for (int fp = 0; fp < NFRAG / 2; fp++) {
                uint32_t r[4];
                ldsm_x4(r, bBuf + (bOff + fp * 16 * G_LDSS + ks * 16) * 2u);
                bf[2 * fp][0] = r[0]; bf[2 * fp][1] = r[1];
                bf[2 * fp + 1][0] = r[2]; bf[2 * fp + 1][1] = r[3];
            }
#pragma unroll
            for (int fm = 0; fm < MFRAG; fm++)
#pragma unroll
                for (int fn = 0; fn < NFRAG; fn++)
                    mma_f16(acc[fm][fn], af[fm], bf[fn]);
        }
    }

    __syncthreads();
    __half* Cs = smh;
    const int m0l = wm * WM;
    const int n0l = wn * WN;
#pragma unroll
    for (int fm = 0; fm < MFRAG; fm++) {
#pragma unroll
        for (int fn = 0; fn < NFRAG; fn++) {
            int lr = m0l + fm * 16 + r4;
            int lc = n0l + fn * 8 + 2 * c4;
            *(__half2*)(Cs + lr * 136 + lc) =
                __floats2half2_rn(acc[fm][fn][0], acc[fm][fn][1]);
            *(__half2*)(Cs + (lr + 8) * 136 + lc) =
                __floats2half2_rn(acc[fm][fn][2], acc[fm][fn][3]);
        }
    }
    __syncthreads();

    const int col = tid & 127;
    const int off = bn - (QQ - 1) + bm;
#pragma unroll 4
    for (int r = tid >> 7; r < 128; r += 2) {
        int k = off + r + col;
        if (k >= 0)
            C[(size_t)(bm + r) * KL + k] = Cs[r * 136 + col];
    }
}

// ---------------------------------------------------------------------------
// Wo GEMM: BN=64 (WN=16) -> 256 CTAs. Grid (16, 16, 1), fp32 out.
// ---------------------------------------------------------------------------
__global__ void __launch_bounds__(256)
wo_kernel(float* __restrict__ out) {
    constexpr int BM = 128, BN = 64, WM = 64, WN = 16;
    constexpr int MFRAG = WM / 16, NFRAG = WN / 8;

    const int bm = blockIdx.y * BM;
    const int bn = blockIdx.x * BN;

    extern __shared__ __half smh[];
    __half* As = smh;
    __half* Bs = smh + 4 * BM * G_LDSS;
    const uint32_t sA_base = smem_to_u32(As);
    const uint32_t sB_base = smem_to_u32(Bs);

    const int tid = threadIdx.x;
    const int lane = tid & 31;
    const int warp = tid >> 5;
    const int wm = warp & 1;
    const int wn = warp >> 1;
    const __half* Ag = g_ctxh + (size_t)bm * UU;
    const __half* Bg = g_woTh + (size_t)bn * UU;
    const int nIter = UU / G_KC;

    auto load_stage = [&](int stage, int buf) {
#pragma unroll
        for (int i = 0; i < 2; i++) {
            int idx = tid + i * 256;
            int row = idx >> 2, ch = idx & 3;
            cp_async16(sA_base + (uint32_t)(buf * BM * G_LDSS + row * G_LDSS + ch * 8) * 2u,
                       Ag + (size_t)row * UU + stage * G_KC + ch * 8);
        }
        {
            int idx = tid;
            int row = idx >> 2, ch = idx & 3;
            cp_async16(sB_base + (uint32_t)(buf * BN * G_LDSS + row * G_LDSS + ch * 8) * 2u,
                       Bg + (size_t)row * UU + stage * G_KC + ch * 8);
        }
    };

    float acc[MFRAG][NFRAG][4];
#pragma unroll
    for (int i = 0; i < MFRAG; i++)
#pragma unroll
        for (int j = 0; j < NFRAG; j++)
#pragma unroll
            for (int v = 0; v < 4; v++) acc[i][j][v] = 0.0f;

    load_stage(0, 0); CP_COMMIT();
    load_stage(1, 1); CP_COMMIT();
    load_stage(2, 2); CP_COMMIT();

    const uint32_t aOff = (uint32_t)((wm * WM + (lane & 15)) * G_LDSS + (lane >> 4) * 8);
    const uint32_t bOff = (uint32_t)((wn * WN + (lane & 7) + (lane >> 4) * 8) * G_LDSS +
                                     ((lane >> 3) & 1) * 8);
    const int r4 = lane >> 2;
    const int c4 = lane & 3;

    for (int it = 0; it < nIter; ++it) {
        CP_WAIT2();
        __syncthreads();
        if (it + 3 < nIter) load_stage(it + 3, (it + 3) & 3);
        CP_COMMIT();

        const uint32_t aBuf = sA_base + (uint32_t)((it & 3) * BM * G_LDSS) * 2u;
        const uint32_t bBuf = sB_base + (uint32_t)((it & 3) * BN * G_LDSS) * 2u;

#pragma unroll
        for (int ks = 0; ks < 2; ks++) {
            uint32_t af[MFRAG][4];
            uint32_t bf[NFRAG][2];
#pragma unroll
            for (int fm = 0; fm < MFRAG; fm++)
                ldsm_x4(af[fm], aBuf + (aOff + fm * 16 * G_LDSS + ks * 16) * 2u);
            {
                uint32_t r[4];
                ldsm_x4(r, bBuf + (bOff + ks * 16) * 2u);
                bf[0][0] = r[0]; bf[0][1] = r[1];
                bf[1][0] = r[2]; bf[1][1] = r[3];
            }
#pragma unroll
            for (int fm = 0; fm < MFRAG; fm++)
#pragma unroll
                for (int fn = 0; fn < NFRAG; fn++)
                    mma_f16(acc[fm][fn], af[fm], bf[fn]);
        }
    }

    const int m0 = bm + wm * WM;
    const int n0 = bn + wn * WN;
#pragma unroll
    for (int fm = 0; fm < MFRAG; fm++) {
#pragma unroll
        for (int fn = 0; fn < NFRAG; fn++) {
            int r = m0 + fm * 16 + r4;
            int cidx = n0 + fn * 8 + c4 * 2;
            *(float2*)(out + (size_t)r * UU + cidx) =
                make_float2(acc[fm][fn][0], acc[fm][fn][1]);
            *(float2*)(out + (size_t)(r + 8) * UU + cidx) =
                make_float2(acc[fm][fn][2], acc[fm][fn][3]);
        }
    }
}

// ---------------------------------------------------------------------------
// Split-K fused fp16 flash attention. Scores pre-scaled in log2 domain;
// P = exp2(s-m) via h2exp2. Mask handling branch-split on lastT (uniform).
// Grid (8*KSPLIT, H, B), 256 threads, 2 CTAs/SM.
// ---------------------------------------------------------------------------
__global__ void __launch_bounds__(256, 2) flash_kernel() {
    extern __shared__ __half smh[];
    __half* sQ  = smh;                  // [128][72]
    __half* sKa = sQ  + 128 * 72;
    __half* sKb = sKa + 128 * 72;
    __half* sV  = sKb + 128 * 72;       // [128 t][72 d]
    __half* sP  = sV  + 128 * 72;       // [128][136]
    const uint32_t uQ  = smem_to_u32(sQ);
    const uint32_t uKa = smem_to_u32(sKa);
    const uint32_t uKb = smem_to_u32(sKb);
    const uint32_t uV  = smem_to_u32(sV);
    const uint32_t uP  = smem_to_u32(sP);

    const int tid = threadIdx.x, lane = tid & 31, warp = tid >> 5;
    const int r4 = lane >> 2, c4 = lane & 3;
    const int qs = (int)blockIdx.x;
    const int qt = 7 - (qs / KSPLIT);
    const int split = qs % KSPLIT;
    const int h = blockIdx.y, b = blockIdx.z;
    const int q0 = qt * 128;
    const int nT = 9 + qt;
    const int t0 = (split * nT) / KSPLIT;
    const int t1 = ((split + 1) * nT) / KSPLIT;

    const __half* gQ = g_qch + ((size_t)b * QQ + q0) * UU + h * 64;
    const __half* gK = g_kh  + (size_t)b * KL * UU + h * 64;
    const __half* gV = g_vh  + (size_t)b * KL * UU + h * 64;
    const __half* gS = g_srh + (((size_t)b * HH + h) * QQ + q0) * KL;

    auto load_k = [&](int t, uint32_t dK) {
        const __half* src = gK + (size_t)t * 128 * UU;
        int i = tid;
#pragma unroll
        for (int rep = 0; rep < 4; rep++, i += 256) {
            int r = i >> 3, c = i & 7;
            cp_async16(dK + (uint32_t)(r * 72 + c * 8) * 2u, src + (size_t)r * UU + c * 8);
        }
    };
    auto load_v = [&](int t) {
        const __half* src = gV + (size_t)t * 128 * UU;
        int i = tid;
#pragma unroll
        for (int rep = 0; rep < 4; rep++, i += 256) {
            int r = i >> 3, c = i & 7;
            cp_async16(uV + (uint32_t)(r * 72 + c * 8) * 2u, src + (size_t)r * UU + c * 8);
        }
    };
    auto load_sr = [&](int t) {
        const __half* src = gS + (size_t)t * 128;
        int i = tid;
#pragma unroll
        for (int rep = 0; rep < 8; rep++, i += 256) {
            int r = i >> 4, c = i & 15;
            cp_async16(uP + (uint32_t)(r * 136 + c * 8) * 2u, src + (size_t)r * KL + c * 8);
        }
    };

    {
        int i = tid;
#pragma unroll
        for (int rep = 0; rep < 4; rep++, i += 256) {
            int r = i >> 3, c = i & 7;
            cp_async16(uQ + (uint32_t)(r * 72 + c * 8) * 2u, gQ + (size_t)r * UU + c * 8);
        }
        load_k(t0, uKa);
        CP_COMMIT();
        load_sr(t0);
        load_v(t0);
        CP_COMMIT();
    }

    const int lr0 = warp * 16 + r4;
    const int qg0 = q0 + lr0, qg1 = qg0 + 8;

    const uint32_t aOffQ = (uint32_t)((warp * 16 + (lane & 15)) * 72 + (lane >> 4) * 8);
    const uint32_t aOffP = (uint32_t)((warp * 16 + (lane & 15)) * 136 + (lane >> 4) * 8);
    const uint32_t bOffK = (uint32_t)(((lane & 7) + (lane >> 4) * 8) * 72 + ((lane >> 3) & 1) * 8);
    const uint32_t bOffV = (uint32_t)((lane & 15) * 72 + (lane >> 4) * 8);

    float m0 = -1e30f, m1 = -1e30f, l0 = 0.f, l1 = 0.f;
    float accO[8][4];
#pragma unroll
    for (int f = 0; f < 8; f++)
#pragma unroll
        for (int v = 0; v < 4; v++) accO[f][v] = 0.f;

    for (int it = t0; it < t1; ++it) {
        const int li = it - t0;
        const uint32_t uK = (li & 1) ? uKb : uKa;
        CP_WAIT1();
        __syncthreads();

        float accS[16][4];
#pragma unroll
        for (int f = 0; f < 16; f++)
#pragma unroll
            for (int v = 0; v < 4; v++) accS[f][v] = 0.f;
#pragma unroll
        for (int ks = 0; ks < 4; ks++) {
            uint32_t a[4];
            ldsm_x4(a, uQ + (aOffQ + ks * 16) * 2u);
#pragma unroll
            for (int fp = 0; fp < 8; fp++) {
                uint32_t r[4];
                ldsm_x4(r, uK + (bOffK + fp * 16 * 72 + ks * 16) * 2u);
                uint32_t b0[2] = {r[0], r[1]};
                uint32_t b1[2] = {r[2], r[3]};
                mma_f16(accS[2 * fp], a, b0);
                mma_f16(accS[2 * fp + 1], a, b1);
            }
        }

        {
            int kn = (it + 1 < t1) ? (it + 1) : (t1 - 1);
            load_k(kn, ((li + 1) & 1) ? uKb : uKa);
            CP_COMMIT();
        }

        CP_WAIT1();
        __syncthreads();

        const int k0 = it * 128;
        const bool lastT = (it == nT - 1);

        __half* p0 = sP + lr0 * 136;
        __half* p1 = p0 + 8 * 136;

        float rm0 = -1e30f, rm1 = -1e30f;
        if (!lastT) {
            // common path: no mask predicates at all
#pragma unroll
            for (int fn = 0; fn < 16; fn++) {
                int kc = fn * 8 + 2 * c4;
                float2 f0 = __half22float2(*(const __half2*)(p0 + kc));
                float2 f1 = __half22float2(*(const __half2*)(p1 + kc));
                float s0 = accS[fn][0] + f0.x;
                float s1 = accS[fn][1] + f0.y;
                float s2 = accS[fn][2] + f1.x;
                float s3 = accS[fn][3] + f1.y;
                accS[fn][0] = s0; accS[fn][1] = s1; accS[fn][2] = s2; accS[fn][3] = s3;
                rm0 = fmaxf(rm0, fmaxf(s0, s1));
                rm1 = fmaxf(rm1, fmaxf(s2, s3));
            }
        } else {
            const int lim0 = MEMN + qg0 - k0;
            const int lim1 = lim0 + 8;
#pragma unroll
            for (int fn = 0; fn < 16; fn++) {
                int kc = fn * 8 + 2 * c4;
                float2 f0 = __half22float2(*(const __half2*)(p0 + kc));
                float2 f1 = __half22float2(*(const __half2*)(p1 + kc));
                float s0 = (kc     <= lim0) ? (accS[fn][0] + f0.x) : -1e30f;
                float s1 = (kc + 1 <= lim0) ? (accS[fn][1] + f0.y) : -1e30f;
                float s2 = (kc     <= lim1) ? (accS[fn][2] + f1.x) : -1e30f;
                float s3 = (kc + 1 <= lim1) ? (accS[fn][3] + f1.y) : -1e30f;
                accS[fn][0] = s0; accS[fn][1] = s1; accS[fn][2] = s2; accS[fn][3] = s3;
                rm0 = fmaxf(rm0, fmaxf(s0, s1));
                rm1 = fmaxf(rm1, fmaxf(s2, s3));
            }
        }
        rm0 = fmaxf(rm0, __shfl_xor_sync(~0u, rm0, 1));
        rm0 = fmaxf(rm0, __shfl_xor_sync(~0u, rm0, 2));
        rm1 = fmaxf(rm1, __shfl_xor_sync(~0u, rm1, 1));
        rm1 = fmaxf(rm1, __shfl_xor_sync(~0u, rm1, 2));
        float mN0 = fmaxf(m0, rm0), mN1 = fmaxf(m1, rm1);
        float al0 = exp2f(m0 - mN0), al1 = exp2f(m1 - mN1);
        m0 = mN0; m1 = mN1;

        float ps0 = 0.f, ps1 = 0.f;
#pragma unroll
        for (int fn = 0; fn < 16; fn++) {
            int kc = fn * 8 + 2 * c4;
            __half2 hp0 = h2exp2(__floats2half2_rn(accS[fn][0] - m0, accS[fn][1] - m0));
            __half2 hp1 = h2exp2(__floats2half2_rn(accS[fn][2] - m1, accS[fn][3] - m1));
            float2 e0 = __half22float2(hp0);
            float2 e1 = __half22float2(hp1);
            ps0 += e0.x + e0.y;
            ps1 += e1.x + e1.y;
            *(__half2*)(p0 + kc) = hp0;
            *(__half2*)(p1 + kc) = hp1;
        }
        ps0 += __shfl_xor_sync(~0u, ps0, 1); ps0 += __shfl_xor_sync(~0u, ps0, 2);
        ps1 += __shfl_xor_sync(~0u, ps1, 1); ps1 += __shfl_xor_sync(~0u, ps1, 2);
        l0 = l0 * al0 + ps0;
        l1 = l1 * al1 + ps1;
#pragma unroll
        for (int f = 0; f < 8; f++) {
            accO[f][0] *= al0; accO[f][1] *= al0;
            accO[f][2] *= al1; accO[f][3] *= al1;
        }
        __syncwarp();

#pragma unroll
        for (int ks = 0; ks < 8; ks++) {
            uint32_t a[4];
            ldsm_x4(a, uP + (aOffP + ks * 16) * 2u);
#pragma unroll
            for (int fp = 0; fp < 4; fp++) {
                uint32_t r[4];
                ldsm_x4t(r, uV + (bOffV + ks * 16 * 72 + fp * 16) * 2u);
                uint32_t b0[2] = {r[0], r[1]};
                uint32_t b1[2] = {r[2], r[3]};
                mma_f16(accO[2 * fp], a, b0);
                mma_f16(accO[2 * fp + 1], a, b1);
            }
        }
        __syncthreads();

        {
            int vn = (it + 1 < t1) ? (it + 1) : (t1 - 1);
            load_sr(vn);
            load_v(vn);
            CP_COMMIT();
        }
    }

    const size_t base0 = ((size_t)b * HH + h) * QQ + qg0;
    const size_t base1 = base0 + 8;
    float* o0 = g_opart + (base0 * KSPLIT + split) * DHH;
    float* o1 = g_opart + (base1 * KSPLIT + split) * DHH;
#pragma unroll
    for (int fn = 0; fn < 8; fn++) {
        int col = fn * 8 + 2 * c4;
        *(float2*)(o0 + col) = make_float2(accO[fn][0], accO[fn][1]);
        *(float2*)(o1 + col) = make_float2(accO[fn][2], accO[fn][3]);
    }
    if (c4 == 0) {
        float* ml0 = g_ml + (base0 * KSPLIT + split) * 2;
        float* ml1 = g_ml + (base1 * KSPLIT + split) * 2;
        ml0[0] = m0; ml0[1] = l0;
        ml1[0] = m1; ml1[1] = l1;
    }
}

// ---------------------------------------------------------------------------
// Combine split-K partials -> ctx (fp16). m values are in log2 domain.
// ---------------------------------------------------------------------------
__global__ void __launch_bounds__(256) combine_kernel() {
    const int col = threadIdx.x & 63;
    const int rloc = threadIdx.x >> 6;
    const int q = blockIdx.x * 4 + rloc;
    const int h = blockIdx.y, b = blockIdx.z;
    const size_t base = ((size_t)b * HH + h) * QQ + q;

    float m[KSPLIT], l[KSPLIT];
#pragma unroll
    for (int s = 0; s < KSPLIT; s++) {
        m[s] = g_ml[(base * KSPLIT + s) * 2 + 0];
        l[s] = g_ml[(base * KSPLIT + s) * 2 + 1];
    }
    float mx = m[0];
#pragma unroll
    for (int s = 1; s < KSPLIT; s++) mx = fmaxf(mx, m[s]);
    float w[KSPLIT], L = 0.f;
#pragma unroll
    for (int s = 0; s < KSPLIT; s++) { w[s] = exp2f(m[s] - mx); L += l[s] * w[s]; }
    const float inv = 1.0f / L;

    float o = 0.f;
#pragma unroll
    for (int s = 0; s < KSPLIT; s++)
        o += g_opart[(base * KSPLIT + s) * DHH + col] * w[s];
    g_ctxh[((size_t)b * QQ + q) * UU + h * 64 + col] = __float2half(o * inv);
}

// ---------------------------------------------------------------------------
// Launch
// ---------------------------------------------------------------------------
extern "C" void kernel_launch(void* const* d_in, const int* in_sizes, int n_in,
                              void* d_out, int out_size) {
    const float* inputs    = (const float*)d_in[0];
    const float* relatives = (const float*)d_in[1];
    const float* memories  = (const float*)d_in[2];
    const float* bias_c    = (const float*)d_in[3];
    const float* bias_r    = (const float*)d_in[4];
    const float* Wq        = (const float*)d_in[5];
    const float* Wkv       = (const float*)d_in[6];
    const float* Wr        = (const float*)d_in[7];
    const float* Wo        = (const float*)d_in[8];
    float* out             = (float*)d_out;

    constexpr int SMEM_G  = 4 * (128 + 128) * G_LDSS * 2;                // 81920
    constexpr int SMEM_WO = 4 * (128 + 64) * G_LDSS * 2;                 // 61440
    constexpr int SMEM_SR = 2 * (128 + 128) * G_LDSS * 2;                // 40960
    constexpr int SMEM_F  = (3 * 128 * 72 + 128 * 72 + 128 * 136) * 2;   // 108544
    cudaFuncSetAttribute((const void*)proj_kernel,
                         cudaFuncAttributeMaxDynamicSharedMemorySize, SMEM_G);
    cudaFuncSetAttribute((const void*)wo_kernel,
                         cudaFuncAttributeMaxDynamicSharedMemorySize, SMEM_WO);
    cudaFuncSetAttribute((const void*)sr_kernel,
                         cudaFuncAttributeMaxDynamicSharedMemorySize, SMEM_SR);
    cudaFuncSetAttribute((const void*)flash_kernel,
                         cudaFuncAttributeMaxDynamicSharedMemorySize, SMEM_F);

    // 0. weight transposes + fp16 prep, single launch
    setup_kernel<<<21504, 256>>>(memories, inputs, relatives, Wq, Wkv, Wr, Wo);

    // 1. merged projections: wkv | wr | wq  (896 CTAs, one launch)
    proj_kernel<<<896, 256, SMEM_G>>>(bias_c, bias_r);

    // 2. SrShift = shifted (qr @ wr^T) — pre-scaled via qr
    sr_kernel<<<dim3(KL / 128, QQ / 128, BB * HH), 256, SMEM_SR>>>();

    // 3. split-K fused fp16 flash (log2-domain softmax) -> partials
    flash_kernel<<<dim3(8 * KSPLIT, HH, BB), 256, SMEM_F>>>();

    // 4. combine partials -> ctx (fp16)
    combine_kernel<<<dim3(QQ / 4, HH, BB), 256>>>();

    // 5. out = ctx @ Wo (fp32 out)
    wo_kernel<<<dim3(UU / 64, (BB * QQ) / 128, 1), 256, SMEM_WO>>>(out);
}